// round 12
// baseline (speedup 1.0000x reference)
#include <cuda_runtime.h>

#define NTN 500000
#define NCN 100000
#define NMN 20000
#define EN  500000

#define NBC2 ((NCN + 511) / 512)    // 196  csr chunks (clients)
#define NBM2 ((NMN + 511) / 512)    // 40   csr chunks (merchants)
#define NBF_C ((NCN + 63) / 64)     // 1563 fused blocks (clients)
#define NBF_M ((NMN + 63) / 64)     // 313  fused blocks (merchants)
#define BUCKET_BLOCKS ((2 * EN + 255) / 256)   // 3907
#define INV_BLOCKS    ((NTN + 255) / 256)      // 1954
#define ZERO_INT4 ((NCN + NMN + 2 * NTN) / 4)  // 280000 int4 to zero

// ---------------- device scratch (no dynamic allocation allowed) ----------------
__device__ int   g_cntC[NCN];
__device__ int   g_cntM[NMN];
__device__ int   g_cntT1[NTN];
__device__ int   g_cntT2[NTN];
__device__ float g_invT1[NTN];
__device__ float g_invT2[NTN];
__device__ int   g_baseC[NCN];
__device__ int   g_baseM[NMN];
__device__ int   g_curC[NCN];
__device__ int   g_curM[NMN];
__device__ int   g_permC[EN];
__device__ int   g_permM[EN];
__device__ int   g_bsumC[512];
__device__ int   g_bbaseC[512];
__device__ int   g_bsumM[512];
__device__ int   g_bbaseM[512];
__device__ unsigned int g_sync1;
__device__ unsigned int g_sync2;
__device__ __align__(256) float g_pC[(size_t)NCN * 2];
__device__ __align__(256) float g_pM[(size_t)NMN * 2];
__device__ __align__(16)  float g_qC[128];    // W1_c2t @ Wf
__device__ __align__(16)  float g_qM[128];    // W1_m2t @ Wf
__device__ __align__(16)  float g_rbC[2];
__device__ __align__(16)  float g_rbM[2];

__device__ __forceinline__ void red_add_v2(float* addr, float x, float y) {
    asm volatile("red.global.add.v2.f32 [%0], {%1, %2};"
                 :: "l"(addr), "f"(x), "f"(y) : "memory");
}

// packed fp32x2 helpers (Blackwell FFMA2 — PTX-only path)
__device__ __forceinline__ unsigned long long pack_dup_f32(float a) {
    unsigned long long r;
    asm("mov.b64 %0, {%1, %1};" : "=l"(r) : "f"(a));
    return r;
}
__device__ __forceinline__ void fma_f32x2(unsigned long long& acc,
                                          unsigned long long a, unsigned long long b) {
    asm("fma.rn.f32x2 %0, %1, %2, %0;" : "+l"(acc) : "l"(a), "l"(b));
}
__device__ __forceinline__ float2 unpack_f32x2(unsigned long long v) {
    float2 f;
    asm("mov.b64 {%0, %1}, %2;" : "=f"(f.x), "=f"(f.y) : "l"(v));
    return f;
}

// ---------------- kernels ----------------

// node 1: zero all counters + sync flags (blocks 1..) and q/rb precompute (block 0)
__global__ void zero_q_kernel(const float* __restrict__ W1c, const float* __restrict__ b1c,
                              const float* __restrict__ W1m, const float* __restrict__ b1m,
                              const float* __restrict__ Wf)
{
    const int tid = threadIdx.x;
    if (blockIdx.x == 0) {
        if (tid < 128) {
            int k = tid >> 1, j = tid & 1;
            float s = 0.f;
            #pragma unroll
            for (int h = 0; h < 64; h++) s = fmaf(W1c[k * 64 + h], Wf[h * 2 + j], s);
            g_qC[tid] = s;
        } else {
            int t = tid - 128;
            int k = t >> 1, j = t & 1;
            float s = 0.f;
            #pragma unroll
            for (int h = 0; h < 64; h++) s = fmaf(W1m[k * 64 + h], Wf[h * 2 + j], s);
            g_qM[t] = s;
        }
        if (tid < 2) {
            float s = 0.f;
            #pragma unroll
            for (int h = 0; h < 64; h++) s = fmaf(b1c[h], Wf[h * 2 + tid], s);
            g_rbC[tid] = s;
        }
        if (tid >= 128 && tid < 130) {
            int j = tid - 128;
            float s = 0.f;
            #pragma unroll
            for (int h = 0; h < 64; h++) s = fmaf(b1m[h], Wf[h * 2 + j], s);
            g_rbM[j] = s;
        }
        if (tid == 0) { g_sync1 = 0; g_sync2 = 0; }
    } else {
        int idx = (blockIdx.x - 1) * 256 + tid;          // int4 index
        const int4 z = make_int4(0, 0, 0, 0);
        const int nC = NCN / 4, nM = NMN / 4, nT = NTN / 4;
        if (idx < nC)                       ((int4*)g_cntC)[idx] = z;
        else if (idx < nC + nM)             ((int4*)g_cntM)[idx - nC] = z;
        else if (idx < nC + nM + nT)        ((int4*)g_cntT1)[idx - nC - nM] = z;
        else if (idx < nC + nM + 2 * nT)    ((int4*)g_cntT2)[idx - nC - nM - nT] = z;
    }
}

// node 2: all four dst histograms in one launch
__global__ void count_all_kernel(const int* __restrict__ d_c2t, const int* __restrict__ d_m2t,
                                 const int* __restrict__ d_t2c, const int* __restrict__ d_t2m)
{
    int i = blockIdx.x * blockDim.x + threadIdx.x;
    if (i < EN)            atomicAdd(&g_cntT1[d_c2t[i]], 1);
    else if (i < 2 * EN)   atomicAdd(&g_cntT2[d_m2t[i - EN]], 1);
    else if (i < 3 * EN)   atomicAdd(&g_cntC[d_t2c[i - 2 * EN]], 1);
    else if (i < 4 * EN)   atomicAdd(&g_cntM[d_t2m[i - 3 * EN]], 1);
}

// node 3: full CSR base build in ONE kernel (grid-resident spin sync).
// grid = NBC2 + NBM2 = 236 blocks of 512 threads — all co-resident on 148 SMs.
__global__ __launch_bounds__(512) void csr_kernel()
{
    __shared__ int s[512];
    const int t = threadIdx.x;
    const bool isC = blockIdx.x < NBC2;
    const int blk = isC ? blockIdx.x : blockIdx.x - NBC2;
    const int* cnt = isC ? g_cntC : g_cntM;
    const int n = isC ? NCN : NMN;
    const int i = blk * 512 + t;
    const int v = (i < n) ? cnt[i] : 0;

    // phase 1: per-block sums
    s[t] = v;
    __syncthreads();
    #pragma unroll
    for (int o = 256; o > 0; o >>= 1) {
        if (t < o) s[t] += s[t + o];
        __syncthreads();
    }
    if (t == 0) {
        (isC ? g_bsumC : g_bsumM)[blk] = s[0];
        __threadfence();
        atomicAdd(&g_sync1, 1u);
    }
    __syncthreads();

    // phase 2: blocks 0 (C) and 1 (M) scan the block sums
    if (blockIdx.x < 2) {
        if (t == 0) { while (atomicAdd(&g_sync1, 0u) < (unsigned)gridDim.x) {} }
        __syncthreads();
        const bool c0 = (blockIdx.x == 0);
        const int* bs = c0 ? g_bsumC : g_bsumM;
        int* bb = c0 ? g_bbaseC : g_bbaseM;
        const int nb = c0 ? NBC2 : NBM2;
        int bv = (t < nb) ? bs[t] : 0;
        s[t] = bv;
        __syncthreads();
        #pragma unroll
        for (int o = 1; o < 512; o <<= 1) {
            int add = (t >= o) ? s[t - o] : 0;
            __syncthreads();
            s[t] += add;
            __syncthreads();
        }
        if (t < nb) bb[t] = s[t] - bv;   // exclusive
        if (t == 0) { __threadfence(); atomicAdd(&g_sync2, 1u); }
    }

    // phase 3: all blocks finalize base/cur
    if (t == 0) { while (atomicAdd(&g_sync2, 0u) < 2u) {} }
    __syncthreads();
    s[t] = v;
    __syncthreads();
    #pragma unroll
    for (int o = 1; o < 512; o <<= 1) {
        int add = (t >= o) ? s[t - o] : 0;
        __syncthreads();
        s[t] += add;
        __syncthreads();
    }
    if (i < n) {
        int b = (isC ? g_bbaseC : g_bbaseM)[blk] + s[t] - v;
        (isC ? g_baseC : g_baseM)[i] = b;
        (isC ? g_curC : g_curM)[i] = b;
    }
}

// node 4: edge counting-sort (both relations) + transaction inv weights + out init
__global__ __launch_bounds__(256) void bucket_inv_kernel(
    const int* __restrict__ s_t2c, const int* __restrict__ d_t2c,
    const int* __restrict__ s_t2m, const int* __restrict__ d_t2m,
    const float* __restrict__ bf, float* __restrict__ out)
{
    if (blockIdx.x < BUCKET_BLOCKS) {
        int i = blockIdx.x * 256 + threadIdx.x;
        if (i < EN) {
            int d = d_t2c[i];
            int pos = atomicAdd(&g_curC[d], 1);
            g_permC[pos] = s_t2c[i];
        } else if (i < 2 * EN) {
            int e = i - EN;
            int d = d_t2m[e];
            int pos = atomicAdd(&g_curM[d], 1);
            g_permM[pos] = s_t2m[e];
        }
    } else {
        int i = (blockIdx.x - BUCKET_BLOCKS) * 256 + threadIdx.x;
        if (i < NTN) {
            int c1 = g_cntT1[i]; g_invT1[i] = 1.0f / (float)(c1 > 0 ? c1 : 1);
            int c2 = g_cntT2[i]; g_invT2[i] = 1.0f / (float)(c2 > 0 ? c2 : 1);
            ((float2*)out)[i] = make_float2(bf[0], bf[1]);
        }
    }
}

// node 5: FUSED (both relations in ONE grid):
//   gather(mean feat rows per dst) -> smem A tile ->
//   h = lrelu(A @ W0 + b0*gate) -> p = h @ q + rb  (2 outputs/row)
// smem floats: sA[64*128] | sW[128*64] | sb[64] | sq[128] | sg[64] | srb[2]
#define FUSED_SMEM_FLOATS (64*128 + 128*64 + 64 + 128 + 64 + 2)
__global__ __launch_bounds__(256) void fused_both_kernel(
    const float* __restrict__ feat,
    const float* __restrict__ W0c, const float* __restrict__ b0c,
    const float* __restrict__ W0m, const float* __restrict__ b0m)
{
    extern __shared__ float smem[];
    float* sA  = smem;                 // 64 x 128 (row-major)
    float* sW  = sA + 64 * 128;        // 128 x 64 (row-major)
    float* sb  = sW + 128 * 64;
    float* sq  = sb + 64;
    float* sg  = sq + 128;
    float* srb = sg + 64;

    const bool isC = blockIdx.x < NBF_C;
    const int blk = isC ? blockIdx.x : blockIdx.x - NBF_C;
    const int M = isC ? NCN : NMN;
    const int* __restrict__ perm = isC ? g_permC : g_permM;
    const int* __restrict__ base = isC ? g_baseC : g_baseM;
    const int* __restrict__ cnt  = isC ? g_cntC  : g_cntM;
    const float* __restrict__ W0 = isC ? W0c : W0m;
    const float* __restrict__ b0 = isC ? b0c : b0m;
    const float* __restrict__ q  = isC ? g_qC : g_qM;
    const float* __restrict__ rb = isC ? g_rbC : g_rbM;
    float* __restrict__ p_out    = isC ? g_pC : g_pM;

    const int tid = threadIdx.x;
    const int row0 = blk * 64;

    // cooperative load of W0 (8192 floats) + small vectors
    #pragma unroll
    for (int l = 0; l < 32; l++) sW[l * 256 + tid] = W0[l * 256 + tid];
    if (tid < 64) sb[tid] = b0[tid];
    else if (tid < 192) sq[tid - 64] = q[tid - 64];
    else if (tid < 194) srb[tid - 192] = rb[tid - 192];

    // gather: each warp accumulates 8 dst rows directly into sA (mean-normalized)
    const int wid = tid >> 5, lane = tid & 31;
    #pragma unroll
    for (int i = 0; i < 8; i++) {
        int rl = wid * 8 + i;
        int gr = row0 + rl;
        float4 a0 = make_float4(0.f, 0.f, 0.f, 0.f);
        float4 a1 = make_float4(0.f, 0.f, 0.f, 0.f);
        float invd = 0.f, gate = 0.f;
        if (gr < M) {
            int b = base[gr];
            int c = cnt[gr];
            invd = 1.0f / (float)(c > 0 ? c : 1);
            gate = (c > 0) ? 1.0f : 0.0f;
            int e = 0;
            for (; e + 1 < c; e += 2) {
                int s0 = __ldg(&perm[b + e]);
                int s1 = __ldg(&perm[b + e + 1]);
                float4 v0 = *(const float4*)(feat + (size_t)s0 * 128 + lane * 4);
                float4 v1 = *(const float4*)(feat + (size_t)s1 * 128 + lane * 4);
                a0.x += v0.x; a0.y += v0.y; a0.z += v0.z; a0.w += v0.w;
                a1.x += v1.x; a1.y += v1.y; a1.z += v1.z; a1.w += v1.w;
            }
            if (e < c) {
                int s0 = __ldg(&perm[b + e]);
                float4 v0 = *(const float4*)(feat + (size_t)s0 * 128 + lane * 4);
                a0.x += v0.x; a0.y += v0.y; a0.z += v0.z; a0.w += v0.w;
            }
        }
        a0.x = (a0.x + a1.x) * invd;
        a0.y = (a0.y + a1.y) * invd;
        a0.z = (a0.z + a1.z) * invd;
        a0.w = (a0.w + a1.w) * invd;
        *(float4*)(sA + rl * 128 + lane * 4) = a0;
        if (lane == 0) sg[rl] = gate;
    }
    __syncthreads();

    // GEMM 64x64 tile, K=128. k unrolled by 4:
    //   a: one LDS.128 per row per 4k (broadcast across lanes)
    //   b: one LDS.128 per k as ulonglong2 -> f32x2 col-pairs for free
    const int tx = tid & 15;   // 4 cols each
    const int ty = tid >> 4;   // 4 rows each
    unsigned long long acc2[4][2];
    #pragma unroll
    for (int i = 0; i < 4; i++) { acc2[i][0] = 0ull; acc2[i][1] = 0ull; }

    #pragma unroll 2
    for (int k0 = 0; k0 < 128; k0 += 4) {
        ulonglong2 bq0 = *(const ulonglong2*)(sW + (k0 + 0) * 64 + tx * 4);
        ulonglong2 bq1 = *(const ulonglong2*)(sW + (k0 + 1) * 64 + tx * 4);
        ulonglong2 bq2 = *(const ulonglong2*)(sW + (k0 + 2) * 64 + tx * 4);
        ulonglong2 bq3 = *(const ulonglong2*)(sW + (k0 + 3) * 64 + tx * 4);
        #pragma unroll
        for (int i = 0; i < 4; i++) {
            float4 a = *(const float4*)(sA + (ty * 4 + i) * 128 + k0);
            unsigned long long ax = pack_dup_f32(a.x);
            fma_f32x2(acc2[i][0], ax, bq0.x);
            fma_f32x2(acc2[i][1], ax, bq0.y);
            unsigned long long ay = pack_dup_f32(a.y);
            fma_f32x2(acc2[i][0], ay, bq1.x);
            fma_f32x2(acc2[i][1], ay, bq1.y);
            unsigned long long az = pack_dup_f32(a.z);
            fma_f32x2(acc2[i][0], az, bq2.x);
            fma_f32x2(acc2[i][1], az, bq2.y);
            unsigned long long aw = pack_dup_f32(a.w);
            fma_f32x2(acc2[i][0], aw, bq3.x);
            fma_f32x2(acc2[i][1], aw, bq3.y);
        }
    }

    // epilogue: bias-gate + lrelu + 2-d projection, reduce over the 16 tx lanes
    #pragma unroll
    for (int i = 0; i < 4; i++) {
        int rl = ty * 4 + i;
        int r = row0 + rl;
        float p0 = 0.f, p1 = 0.f;
        if (r < M) {
            float gate = sg[rl];
            float2 v01 = unpack_f32x2(acc2[i][0]);
            float2 v23 = unpack_f32x2(acc2[i][1]);
            float v[4] = { v01.x, v01.y, v23.x, v23.y };
            #pragma unroll
            for (int j = 0; j < 4; j++) {
                int col = tx * 4 + j;
                float h = v[j] + sb[col] * gate;
                h = (h > 0.f) ? h : 0.01f * h;      // leaky_relu
                p0 = fmaf(h, sq[col * 2],     p0);
                p1 = fmaf(h, sq[col * 2 + 1], p1);
            }
        }
        #pragma unroll
        for (int o = 8; o >= 1; o >>= 1) {
            p0 += __shfl_xor_sync(0xffffffffu, p0, o);
            p1 += __shfl_xor_sync(0xffffffffu, p1, o);
        }
        if (tx == 0 && r < M) {
            p_out[(size_t)r * 2]     = p0 + srb[0];
            p_out[(size_t)r * 2 + 1] = p1 + srb[1];
        }
    }
}

// node 6: layer-1 scatter: both relations, one thread per edge, 8 B payload
__global__ __launch_bounds__(256) void scatter2_kernel(
    const int* __restrict__ s_c2t, const int* __restrict__ d_c2t,
    const int* __restrict__ s_m2t, const int* __restrict__ d_m2t,
    float* __restrict__ out)
{
    int i = blockIdx.x * blockDim.x + threadIdx.x;
    if (i >= 2 * EN) return;
    int s, d;
    const float* p;
    float w;
    if (i < EN) {
        s = s_c2t[i]; d = d_c2t[i];
        p = g_pC + (size_t)s * 2;
        w = g_invT1[d];
    } else {
        int e = i - EN;
        s = s_m2t[e]; d = d_m2t[e];
        p = g_pM + (size_t)s * 2;
        w = g_invT2[d];
    }
    float2 v = *(const float2*)p;
    red_add_v2(out + (size_t)d * 2, v.x * w, v.y * w);
}

// ---------------- launch ----------------
extern "C" void kernel_launch(void* const* d_in, const int* in_sizes, int n_in,
                              void* d_out, int out_size)
{
    (void)in_sizes; (void)n_in; (void)out_size;

    const float* feat   = (const float*)d_in[0];
    const int* s_c2t    = (const int*)d_in[3];
    const int* d_c2t    = (const int*)d_in[4];
    const int* s_m2t    = (const int*)d_in[5];
    const int* d_m2t    = (const int*)d_in[6];
    const int* s_t2c    = (const int*)d_in[7];
    const int* d_t2c    = (const int*)d_in[8];
    const int* s_t2m    = (const int*)d_in[9];
    const int* d_t2m    = (const int*)d_in[10];
    const float* W1_c2t = (const float*)d_in[13];
    const float* b1_c2t = (const float*)d_in[14];
    const float* W1_m2t = (const float*)d_in[17];
    const float* b1_m2t = (const float*)d_in[18];
    const float* W0_t2c = (const float*)d_in[19];
    const float* b0_t2c = (const float*)d_in[20];
    const float* W0_t2m = (const float*)d_in[23];
    const float* b0_t2m = (const float*)d_in[24];
    const float* Wf     = (const float*)d_in[27];
    const float* bf     = (const float*)d_in[28];
    float* out = (float*)d_out;

    const int fused_smem = FUSED_SMEM_FLOATS * (int)sizeof(float);
    cudaFuncSetAttribute(fused_both_kernel,
                         cudaFuncAttributeMaxDynamicSharedMemorySize, fused_smem);

    // node 1: zero counters/sync + precompute q/rb
    zero_q_kernel<<<1 + (ZERO_INT4 + 255) / 256, 256>>>(
        W1_c2t, b1_c2t, W1_m2t, b1_m2t, Wf);

    // node 2: all dst histograms
    count_all_kernel<<<(4 * EN + 255) / 256, 256>>>(d_c2t, d_m2t, d_t2c, d_t2m);

    // node 3: CSR bases (single kernel, internal grid sync)
    csr_kernel<<<NBC2 + NBM2, 512>>>();

    // node 4: counting-sort edges + transaction inv weights + out init
    bucket_inv_kernel<<<BUCKET_BLOCKS + INV_BLOCKS, 256>>>(
        s_t2c, d_t2c, s_t2m, d_t2m, bf, out);

    // node 5: fused gather + GEMM + projection (both relations)
    fused_both_kernel<<<NBF_C + NBF_M, 256, fused_smem>>>(
        feat, W0_t2c, b0_t2c, W0_t2m, b0_t2m);

    // node 6: layer-1 scatter straight into the output
    scatter2_kernel<<<(2 * EN + 255) / 256, 256>>>(s_c2t, d_c2t, s_m2t, d_m2t, out);
}

// round 13
// speedup vs baseline: 1.2925x; 1.2925x over previous
#include <cuda_runtime.h>

#define NTN 500000
#define NCN 100000
#define NMN 20000
#define EN  500000

#define NB_C ((NCN + 255) / 256)   // 391
#define NB_M ((NMN + 255) / 256)   // 79
#define NBF_C ((NCN + 63) / 64)    // 1563 fused blocks (clients)
#define NBF_M ((NMN + 63) / 64)    // 313  fused blocks (merchants)

// ---------------- device scratch (no dynamic allocation allowed) ----------------
__device__ int   g_cntC[NCN];
__device__ int   g_cntM[NMN];
__device__ int   g_cntT1[NTN];
__device__ int   g_cntT2[NTN];
__device__ float g_invT1[NTN];
__device__ float g_invT2[NTN];
__device__ int   g_baseC[NCN];
__device__ int   g_baseM[NMN];
__device__ int   g_curC[NCN];
__device__ int   g_curM[NMN];
__device__ int   g_permC[EN];
__device__ int   g_permM[EN];
__device__ int   g_bsumC[512];
__device__ int   g_bbaseC[512];
__device__ int   g_bsumM[512];
__device__ int   g_bbaseM[512];
__device__ __align__(256) float g_pC[(size_t)NCN * 2];
__device__ __align__(256) float g_pM[(size_t)NMN * 2];
__device__ __align__(16)  float g_qC[128];    // W1_c2t @ Wf
__device__ __align__(16)  float g_qM[128];    // W1_m2t @ Wf
__device__ __align__(16)  float g_rbC[2];
__device__ __align__(16)  float g_rbM[2];

__device__ __forceinline__ void red_add_v2(float* addr, float x, float y) {
    asm volatile("red.global.add.v2.f32 [%0], {%1, %2};"
                 :: "l"(addr), "f"(x), "f"(y) : "memory");
}

// packed fp32x2 helpers (Blackwell FFMA2 — PTX-only path)
__device__ __forceinline__ unsigned long long pack_dup_f32(float a) {
    unsigned long long r;
    asm("mov.b64 %0, {%1, %1};" : "=l"(r) : "f"(a));
    return r;
}
__device__ __forceinline__ void fma_f32x2(unsigned long long& acc,
                                          unsigned long long a, unsigned long long b) {
    asm("fma.rn.f32x2 %0, %1, %2, %0;" : "+l"(acc) : "l"(a), "l"(b));
}
__device__ __forceinline__ float2 unpack_f32x2(unsigned long long v) {
    float2 f;
    asm("mov.b64 {%0, %1}, %2;" : "=f"(f.x), "=f"(f.y) : "l"(v));
    return f;
}

// ---------------- kernels ----------------

// all four dst histograms in one launch
__global__ void count_all_kernel(const int* __restrict__ d_c2t, const int* __restrict__ d_m2t,
                                 const int* __restrict__ d_t2c, const int* __restrict__ d_t2m)
{
    int i = blockIdx.x * blockDim.x + threadIdx.x;
    if (i < EN)            atomicAdd(&g_cntT1[d_c2t[i]], 1);
    else if (i < 2 * EN)   atomicAdd(&g_cntT2[d_m2t[i - EN]], 1);
    else if (i < 3 * EN)   atomicAdd(&g_cntC[d_t2c[i - 2 * EN]], 1);
    else if (i < 4 * EN)   atomicAdd(&g_cntM[d_t2m[i - 3 * EN]], 1);
}

// inv weights for transactions + output init to bf
__global__ void inv_out_kernel(const float* __restrict__ bf, float* __restrict__ out)
{
    int i = blockIdx.x * blockDim.x + threadIdx.x;
    if (i < NTN) {
        int c1 = g_cntT1[i]; g_invT1[i] = 1.0f / (float)(c1 > 0 ? c1 : 1);
        int c2 = g_cntT2[i]; g_invT2[i] = 1.0f / (float)(c2 > 0 ? c2 : 1);
        ((float2*)out)[i] = make_float2(bf[0], bf[1]);
    }
}

// ---- CSR build (both relations in each launch) ----
__global__ void blocksum_both_kernel()
{
    __shared__ int s[256];
    bool isC = blockIdx.x < NB_C;
    int blk = isC ? blockIdx.x : blockIdx.x - NB_C;
    const int* cnt = isC ? g_cntC : g_cntM;
    int n = isC ? NCN : NMN;
    int i = blk * 256 + threadIdx.x;
    s[threadIdx.x] = (i < n) ? cnt[i] : 0;
    __syncthreads();
    #pragma unroll
    for (int o = 128; o > 0; o >>= 1) {
        if (threadIdx.x < o) s[threadIdx.x] += s[threadIdx.x + o];
        __syncthreads();
    }
    if (threadIdx.x == 0) (isC ? g_bsumC : g_bsumM)[blk] = s[0];
}

__global__ void scan_both_kernel()
{
    __shared__ int s[512];
    bool isC = blockIdx.x == 0;
    const int* bsum = isC ? g_bsumC : g_bsumM;
    int* bbase = isC ? g_bbaseC : g_bbaseM;
    int nb = isC ? NB_C : NB_M;
    int t = threadIdx.x;
    int v = (t < nb) ? bsum[t] : 0;
    s[t] = v;
    __syncthreads();
    #pragma unroll
    for (int o = 1; o < 512; o <<= 1) {
        int add = (t >= o) ? s[t - o] : 0;
        __syncthreads();
        s[t] += add;
        __syncthreads();
    }
    if (t < nb) bbase[t] = s[t] - v;   // exclusive
}

__global__ void finalize_both_kernel()
{
    __shared__ int s[256];
    bool isC = blockIdx.x < NB_C;
    int blk = isC ? blockIdx.x : blockIdx.x - NB_C;
    const int* cnt = isC ? g_cntC : g_cntM;
    const int* bbase = isC ? g_bbaseC : g_bbaseM;
    int* base = isC ? g_baseC : g_baseM;
    int* cur = isC ? g_curC : g_curM;
    int n = isC ? NCN : NMN;
    int t = threadIdx.x;
    int i = blk * 256 + t;
    int v = (i < n) ? cnt[i] : 0;
    s[t] = v;
    __syncthreads();
    #pragma unroll
    for (int o = 1; o < 256; o <<= 1) {
        int add = (t >= o) ? s[t - o] : 0;
        __syncthreads();
        s[t] += add;
        __syncthreads();
    }
    if (i < n) {
        int b = bbase[blk] + s[t] - v;
        base[i] = b;
        cur[i]  = b;
    }
}

__global__ void bucket_both_kernel(const int* __restrict__ s_t2c, const int* __restrict__ d_t2c,
                                   const int* __restrict__ s_t2m, const int* __restrict__ d_t2m)
{
    int i = blockIdx.x * blockDim.x + threadIdx.x;
    if (i < EN) {
        int d = d_t2c[i];
        int pos = atomicAdd(&g_curC[d], 1);
        g_permC[pos] = s_t2c[i];
    } else if (i < 2 * EN) {
        int e = i - EN;
        int d = d_t2m[e];
        int pos = atomicAdd(&g_curM[d], 1);
        g_permM[pos] = s_t2m[e];
    }
}

// q = W1 @ Wf (64x64 @ 64x2), rb = b1 @ Wf — tiny, one block
__global__ void precompute_q_kernel(const float* __restrict__ W1c, const float* __restrict__ b1c,
                                    const float* __restrict__ W1m, const float* __restrict__ b1m,
                                    const float* __restrict__ Wf)
{
    int tid = threadIdx.x;  // 256 threads
    if (tid < 128) {
        int k = tid >> 1, j = tid & 1;
        float s = 0.f;
        #pragma unroll
        for (int h = 0; h < 64; h++) s = fmaf(W1c[k * 64 + h], Wf[h * 2 + j], s);
        g_qC[tid] = s;
    } else {
        int t = tid - 128;
        int k = t >> 1, j = t & 1;
        float s = 0.f;
        #pragma unroll
        for (int h = 0; h < 64; h++) s = fmaf(W1m[k * 64 + h], Wf[h * 2 + j], s);
        g_qM[t] = s;
    }
    if (tid < 2) {
        float s = 0.f;
        #pragma unroll
        for (int h = 0; h < 64; h++) s = fmaf(b1c[h], Wf[h * 2 + tid], s);
        g_rbC[tid] = s;
    }
    if (tid >= 128 && tid < 130) {
        int j = tid - 128;
        float s = 0.f;
        #pragma unroll
        for (int h = 0; h < 64; h++) s = fmaf(b1m[h], Wf[h * 2 + j], s);
        g_rbM[j] = s;
    }
}

// ---- FUSED (both relations in ONE grid):
//   gather(mean feat rows per dst) -> smem A tile ->
//   h = lrelu(A @ W0 + b0*gate) -> p = h @ q + rb  (2 outputs/row)
// smem floats: sA[64*128] | sW[128*64] | sb[64] | sq[128] | sg[64] | srb[2]
#define FUSED_SMEM_FLOATS (64*128 + 128*64 + 64 + 128 + 64 + 2)
__global__ __launch_bounds__(256) void fused_both_kernel(
    const float* __restrict__ feat,
    const float* __restrict__ W0c, const float* __restrict__ b0c,
    const float* __restrict__ W0m, const float* __restrict__ b0m)
{
    extern __shared__ float smem[];
    float* sA  = smem;                 // 64 x 128 (row-major)
    float* sW  = sA + 64 * 128;        // 128 x 64 (row-major)
    float* sb  = sW + 128 * 64;
    float* sq  = sb + 64;
    float* sg  = sq + 128;
    float* srb = sg + 64;

    const bool isC = blockIdx.x < NBF_C;
    const int blk = isC ? blockIdx.x : blockIdx.x - NBF_C;
    const int M = isC ? NCN : NMN;
    const int* __restrict__ perm = isC ? g_permC : g_permM;
    const int* __restrict__ base = isC ? g_baseC : g_baseM;
    const int* __restrict__ cnt  = isC ? g_cntC  : g_cntM;
    const float* __restrict__ W0 = isC ? W0c : W0m;
    const float* __restrict__ b0 = isC ? b0c : b0m;
    const float* __restrict__ q  = isC ? g_qC : g_qM;
    const float* __restrict__ rb = isC ? g_rbC : g_rbM;
    float* __restrict__ p_out    = isC ? g_pC : g_pM;

    const int tid = threadIdx.x;
    const int row0 = blk * 64;

    // cooperative load of W0 (8192 floats) + small vectors
    #pragma unroll
    for (int l = 0; l < 32; l++) sW[l * 256 + tid] = W0[l * 256 + tid];
    if (tid < 64) sb[tid] = b0[tid];
    else if (tid < 192) sq[tid - 64] = q[tid - 64];
    else if (tid < 194) srb[tid - 192] = rb[tid - 192];

    // gather: each warp accumulates 8 dst rows directly into sA (mean-normalized)
    const int wid = tid >> 5, lane = tid & 31;
    #pragma unroll
    for (int i = 0; i < 8; i++) {
        int rl = wid * 8 + i;
        int gr = row0 + rl;
        float4 a0 = make_float4(0.f, 0.f, 0.f, 0.f);
        float4 a1 = make_float4(0.f, 0.f, 0.f, 0.f);
        float invd = 0.f, gate = 0.f;
        if (gr < M) {
            int b = base[gr];
            int c = cnt[gr];
            invd = 1.0f / (float)(c > 0 ? c : 1);
            gate = (c > 0) ? 1.0f : 0.0f;
            int e = 0;
            for (; e + 1 < c; e += 2) {
                int s0 = __ldg(&perm[b + e]);
                int s1 = __ldg(&perm[b + e + 1]);
                float4 v0 = *(const float4*)(feat + (size_t)s0 * 128 + lane * 4);
                float4 v1 = *(const float4*)(feat + (size_t)s1 * 128 + lane * 4);
                a0.x += v0.x; a0.y += v0.y; a0.z += v0.z; a0.w += v0.w;
                a1.x += v1.x; a1.y += v1.y; a1.z += v1.z; a1.w += v1.w;
            }
            if (e < c) {
                int s0 = __ldg(&perm[b + e]);
                float4 v0 = *(const float4*)(feat + (size_t)s0 * 128 + lane * 4);
                a0.x += v0.x; a0.y += v0.y; a0.z += v0.z; a0.w += v0.w;
            }
        }
        a0.x = (a0.x + a1.x) * invd;
        a0.y = (a0.y + a1.y) * invd;
        a0.z = (a0.z + a1.z) * invd;
        a0.w = (a0.w + a1.w) * invd;
        *(float4*)(sA + rl * 128 + lane * 4) = a0;
        if (lane == 0) sg[rl] = gate;
    }
    __syncthreads();

    // GEMM 64x64 tile, K=128. k unrolled by 4:
    //   a: one LDS.128 per row per 4k (broadcast across lanes)
    //   b: one LDS.128 per k as ulonglong2 -> f32x2 col-pairs for free
    const int tx = tid & 15;   // 4 cols each
    const int ty = tid >> 4;   // 4 rows each
    unsigned long long acc2[4][2];
    #pragma unroll
    for (int i = 0; i < 4; i++) { acc2[i][0] = 0ull; acc2[i][1] = 0ull; }

    #pragma unroll 2
    for (int k0 = 0; k0 < 128; k0 += 4) {
        ulonglong2 bq0 = *(const ulonglong2*)(sW + (k0 + 0) * 64 + tx * 4);
        ulonglong2 bq1 = *(const ulonglong2*)(sW + (k0 + 1) * 64 + tx * 4);
        ulonglong2 bq2 = *(const ulonglong2*)(sW + (k0 + 2) * 64 + tx * 4);
        ulonglong2 bq3 = *(const ulonglong2*)(sW + (k0 + 3) * 64 + tx * 4);
        #pragma unroll
        for (int i = 0; i < 4; i++) {
            float4 a = *(const float4*)(sA + (ty * 4 + i) * 128 + k0);
            unsigned long long ax = pack_dup_f32(a.x);
            fma_f32x2(acc2[i][0], ax, bq0.x);
            fma_f32x2(acc2[i][1], ax, bq0.y);
            unsigned long long ay = pack_dup_f32(a.y);
            fma_f32x2(acc2[i][0], ay, bq1.x);
            fma_f32x2(acc2[i][1], ay, bq1.y);
            unsigned long long az = pack_dup_f32(a.z);
            fma_f32x2(acc2[i][0], az, bq2.x);
            fma_f32x2(acc2[i][1], az, bq2.y);
            unsigned long long aw = pack_dup_f32(a.w);
            fma_f32x2(acc2[i][0], aw, bq3.x);
            fma_f32x2(acc2[i][1], aw, bq3.y);
        }
    }

    // epilogue: bias-gate + lrelu + 2-d projection, reduce over the 16 tx lanes
    #pragma unroll
    for (int i = 0; i < 4; i++) {
        int rl = ty * 4 + i;
        int r = row0 + rl;
        float p0 = 0.f, p1 = 0.f;
        if (r < M) {
            float gate = sg[rl];
            float2 v01 = unpack_f32x2(acc2[i][0]);
            float2 v23 = unpack_f32x2(acc2[i][1]);
            float v[4] = { v01.x, v01.y, v23.x, v23.y };
            #pragma unroll
            for (int j = 0; j < 4; j++) {
                int col = tx * 4 + j;
                float h = v[j] + sb[col] * gate;
                h = (h > 0.f) ? h : 0.01f * h;      // leaky_relu
                p0 = fmaf(h, sq[col * 2],     p0);
                p1 = fmaf(h, sq[col * 2 + 1], p1);
            }
        }
        #pragma unroll
        for (int o = 8; o >= 1; o >>= 1) {
            p0 += __shfl_xor_sync(0xffffffffu, p0, o);
            p1 += __shfl_xor_sync(0xffffffffu, p1, o);
        }
        if (tx == 0 && r < M) {
            p_out[(size_t)r * 2]     = p0 + srb[0];
            p_out[(size_t)r * 2 + 1] = p1 + srb[1];
        }
    }
}

// layer-1 scatter: both relations, one thread per edge, 8 B payload
__global__ __launch_bounds__(256) void scatter2_kernel(
    const int* __restrict__ s_c2t, const int* __restrict__ d_c2t,
    const int* __restrict__ s_m2t, const int* __restrict__ d_m2t,
    float* __restrict__ out)
{
    int i = blockIdx.x * blockDim.x + threadIdx.x;
    if (i >= 2 * EN) return;
    int s, d;
    const float* p;
    float w;
    if (i < EN) {
        s = s_c2t[i]; d = d_c2t[i];
        p = g_pC + (size_t)s * 2;
        w = g_invT1[d];
    } else {
        int e = i - EN;
        s = s_m2t[e]; d = d_m2t[e];
        p = g_pM + (size_t)s * 2;
        w = g_invT2[d];
    }
    float2 v = *(const float2*)p;
    red_add_v2(out + (size_t)d * 2, v.x * w, v.y * w);
}

// ---------------- launch ----------------
extern "C" void kernel_launch(void* const* d_in, const int* in_sizes, int n_in,
                              void* d_out, int out_size)
{
    (void)in_sizes; (void)n_in; (void)out_size;

    const float* feat   = (const float*)d_in[0];
    const int* s_c2t    = (const int*)d_in[3];
    const int* d_c2t    = (const int*)d_in[4];
    const int* s_m2t    = (const int*)d_in[5];
    const int* d_m2t    = (const int*)d_in[6];
    const int* s_t2c    = (const int*)d_in[7];
    const int* d_t2c    = (const int*)d_in[8];
    const int* s_t2m    = (const int*)d_in[9];
    const int* d_t2m    = (const int*)d_in[10];
    const float* W1_c2t = (const float*)d_in[13];
    const float* b1_c2t = (const float*)d_in[14];
    const float* W1_m2t = (const float*)d_in[17];
    const float* b1_m2t = (const float*)d_in[18];
    const float* W0_t2c = (const float*)d_in[19];
    const float* b0_t2c = (const float*)d_in[20];
    const float* W0_t2m = (const float*)d_in[23];
    const float* b0_t2m = (const float*)d_in[24];
    const float* Wf     = (const float*)d_in[27];
    const float* bf     = (const float*)d_in[28];
    float* out = (float*)d_out;

    void *cntC_p, *cntM_p, *cntT1_p, *cntT2_p;
    cudaGetSymbolAddress(&cntC_p,  g_cntC);
    cudaGetSymbolAddress(&cntM_p,  g_cntM);
    cudaGetSymbolAddress(&cntT1_p, g_cntT1);
    cudaGetSymbolAddress(&cntT2_p, g_cntT2);

    const int fused_smem = FUSED_SMEM_FLOATS * (int)sizeof(float);
    cudaFuncSetAttribute(fused_both_kernel,
                         cudaFuncAttributeMaxDynamicSharedMemorySize, fused_smem);

    cudaMemsetAsync(cntC_p,  0, sizeof(g_cntC),  0);
    cudaMemsetAsync(cntM_p,  0, sizeof(g_cntM),  0);
    cudaMemsetAsync(cntT1_p, 0, sizeof(g_cntT1), 0);
    cudaMemsetAsync(cntT2_p, 0, sizeof(g_cntT2), 0);

    count_all_kernel<<<(4 * EN + 255) / 256, 256>>>(d_c2t, d_m2t, d_t2c, d_t2m);
    precompute_q_kernel<<<1, 256>>>(W1_c2t, b1_c2t, W1_m2t, b1_m2t, Wf);
    inv_out_kernel<<<(NTN + 255) / 256, 256>>>(bf, out);

    // CSR build (C and M in the same launches)
    blocksum_both_kernel<<<NB_C + NB_M, 256>>>();
    scan_both_kernel<<<2, 512>>>();
    finalize_both_kernel<<<NB_C + NB_M, 256>>>();
    bucket_both_kernel<<<(2 * EN + 255) / 256, 256>>>(s_t2c, d_t2c, s_t2m, d_t2m);

    // fused gather + GEMM + projection, both relations in one grid
    fused_both_kernel<<<NBF_C + NBF_M, 256, fused_smem>>>(
        feat, W0_t2c, b0_t2c, W0_t2m, b0_t2m);

    // layer-1 scatter straight into the output
    scatter2_kernel<<<(2 * EN + 255) / 256, 256>>>(s_c2t, d_c2t, s_m2t, d_m2t, out);
}

// round 14
// speedup vs baseline: 1.3417x; 1.0381x over previous
#include <cuda_runtime.h>

#define NTN 500000
#define NCN 100000
#define NMN 20000
#define EN  500000

#define NB_C ((NCN + 255) / 256)   // 391
#define NB_M ((NMN + 255) / 256)   // 79
#define NBF_C ((NCN + 63) / 64)    // 1563 fused blocks (clients)
#define NBF_M ((NMN + 63) / 64)    // 313  fused blocks (merchants)

#define SA_PITCH 132               // 64 rows x 132 (128 + pad 4) — conflict-free A frags
#define SW_PITCH 72                // 128 rows x 72 (64 + pad 8) — conflict-free B frags

// ---------------- device scratch (no dynamic allocation allowed) ----------------
__device__ int   g_cntC[NCN];
__device__ int   g_cntM[NMN];
__device__ int   g_cntT1[NTN];
__device__ int   g_cntT2[NTN];
__device__ float g_invT1[NTN];
__device__ float g_invT2[NTN];
__device__ int   g_baseC[NCN];
__device__ int   g_baseM[NMN];
__device__ int   g_curC[NCN];
__device__ int   g_curM[NMN];
__device__ int   g_permC[EN];
__device__ int   g_permM[EN];
__device__ int   g_bsumC[512];
__device__ int   g_bbaseC[512];
__device__ int   g_bsumM[512];
__device__ int   g_bbaseM[512];
__device__ __align__(256) float g_pC[(size_t)NCN * 2];
__device__ __align__(256) float g_pM[(size_t)NMN * 2];
__device__ __align__(16)  float g_qC[128];    // W1_c2t @ Wf
__device__ __align__(16)  float g_qM[128];    // W1_m2t @ Wf
__device__ __align__(16)  float g_rbC[2];
__device__ __align__(16)  float g_rbM[2];

__device__ __forceinline__ void red_add_v2(float* addr, float x, float y) {
    asm volatile("red.global.add.v2.f32 [%0], {%1, %2};"
                 :: "l"(addr), "f"(x), "f"(y) : "memory");
}

// ---- tf32 tensor-core helpers ----
__device__ __forceinline__ unsigned int f2tf32(float x) {
    unsigned int r;
    asm("cvt.rna.tf32.f32 %0, %1;" : "=r"(r) : "f"(x));
    return r;
}
__device__ __forceinline__ void mma_tf32(float* d,
    unsigned int a0, unsigned int a1, unsigned int a2, unsigned int a3,
    unsigned int b0, unsigned int b1)
{
    asm volatile(
        "mma.sync.aligned.m16n8k8.row.col.f32.tf32.tf32.f32 "
        "{%0,%1,%2,%3}, {%4,%5,%6,%7}, {%8,%9}, {%0,%1,%2,%3};"
        : "+f"(d[0]), "+f"(d[1]), "+f"(d[2]), "+f"(d[3])
        : "r"(a0), "r"(a1), "r"(a2), "r"(a3), "r"(b0), "r"(b1));
}

// ---------------- kernels ----------------

// all four dst histograms in one launch
__global__ void count_all_kernel(const int* __restrict__ d_c2t, const int* __restrict__ d_m2t,
                                 const int* __restrict__ d_t2c, const int* __restrict__ d_t2m)
{
    int i = blockIdx.x * blockDim.x + threadIdx.x;
    if (i < EN)            atomicAdd(&g_cntT1[d_c2t[i]], 1);
    else if (i < 2 * EN)   atomicAdd(&g_cntT2[d_m2t[i - EN]], 1);
    else if (i < 3 * EN)   atomicAdd(&g_cntC[d_t2c[i - 2 * EN]], 1);
    else if (i < 4 * EN)   atomicAdd(&g_cntM[d_t2m[i - 3 * EN]], 1);
}

// inv weights for transactions + output init to bf
__global__ void inv_out_kernel(const float* __restrict__ bf, float* __restrict__ out)
{
    int i = blockIdx.x * blockDim.x + threadIdx.x;
    if (i < NTN) {
        int c1 = g_cntT1[i]; g_invT1[i] = 1.0f / (float)(c1 > 0 ? c1 : 1);
        int c2 = g_cntT2[i]; g_invT2[i] = 1.0f / (float)(c2 > 0 ? c2 : 1);
        ((float2*)out)[i] = make_float2(bf[0], bf[1]);
    }
}

// ---- CSR build (both relations in each launch) ----
__global__ void blocksum_both_kernel()
{
    __shared__ int s[256];
    bool isC = blockIdx.x < NB_C;
    int blk = isC ? blockIdx.x : blockIdx.x - NB_C;
    const int* cnt = isC ? g_cntC : g_cntM;
    int n = isC ? NCN : NMN;
    int i = blk * 256 + threadIdx.x;
    s[threadIdx.x] = (i < n) ? cnt[i] : 0;
    __syncthreads();
    #pragma unroll
    for (int o = 128; o > 0; o >>= 1) {
        if (threadIdx.x < o) s[threadIdx.x] += s[threadIdx.x + o];
        __syncthreads();
    }
    if (threadIdx.x == 0) (isC ? g_bsumC : g_bsumM)[blk] = s[0];
}

__global__ void scan_both_kernel()
{
    __shared__ int s[512];
    bool isC = blockIdx.x == 0;
    const int* bsum = isC ? g_bsumC : g_bsumM;
    int* bbase = isC ? g_bbaseC : g_bbaseM;
    int nb = isC ? NB_C : NB_M;
    int t = threadIdx.x;
    int v = (t < nb) ? bsum[t] : 0;
    s[t] = v;
    __syncthreads();
    #pragma unroll
    for (int o = 1; o < 512; o <<= 1) {
        int add = (t >= o) ? s[t - o] : 0;
        __syncthreads();
        s[t] += add;
        __syncthreads();
    }
    if (t < nb) bbase[t] = s[t] - v;   // exclusive
}

__global__ void finalize_both_kernel()
{
    __shared__ int s[256];
    bool isC = blockIdx.x < NB_C;
    int blk = isC ? blockIdx.x : blockIdx.x - NB_C;
    const int* cnt = isC ? g_cntC : g_cntM;
    const int* bbase = isC ? g_bbaseC : g_bbaseM;
    int* base = isC ? g_baseC : g_baseM;
    int* cur = isC ? g_curC : g_curM;
    int n = isC ? NCN : NMN;
    int t = threadIdx.x;
    int i = blk * 256 + t;
    int v = (i < n) ? cnt[i] : 0;
    s[t] = v;
    __syncthreads();
    #pragma unroll
    for (int o = 1; o < 256; o <<= 1) {
        int add = (t >= o) ? s[t - o] : 0;
        __syncthreads();
        s[t] += add;
        __syncthreads();
    }
    if (i < n) {
        int b = bbase[blk] + s[t] - v;
        base[i] = b;
        cur[i]  = b;
    }
}

__global__ void bucket_both_kernel(const int* __restrict__ s_t2c, const int* __restrict__ d_t2c,
                                   const int* __restrict__ s_t2m, const int* __restrict__ d_t2m)
{
    int i = blockIdx.x * blockDim.x + threadIdx.x;
    if (i < EN) {
        int d = d_t2c[i];
        int pos = atomicAdd(&g_curC[d], 1);
        g_permC[pos] = s_t2c[i];
    } else if (i < 2 * EN) {
        int e = i - EN;
        int d = d_t2m[e];
        int pos = atomicAdd(&g_curM[d], 1);
        g_permM[pos] = s_t2m[e];
    }
}

// q = W1 @ Wf (64x64 @ 64x2), rb = b1 @ Wf — tiny, one block
__global__ void precompute_q_kernel(const float* __restrict__ W1c, const float* __restrict__ b1c,
                                    const float* __restrict__ W1m, const float* __restrict__ b1m,
                                    const float* __restrict__ Wf)
{
    int tid = threadIdx.x;  // 256 threads
    if (tid < 128) {
        int k = tid >> 1, j = tid & 1;
        float s = 0.f;
        #pragma unroll
        for (int h = 0; h < 64; h++) s = fmaf(W1c[k * 64 + h], Wf[h * 2 + j], s);
        g_qC[tid] = s;
    } else {
        int t = tid - 128;
        int k = t >> 1, j = t & 1;
        float s = 0.f;
        #pragma unroll
        for (int h = 0; h < 64; h++) s = fmaf(W1m[k * 64 + h], Wf[h * 2 + j], s);
        g_qM[t] = s;
    }
    if (tid < 2) {
        float s = 0.f;
        #pragma unroll
        for (int h = 0; h < 64; h++) s = fmaf(b1c[h], Wf[h * 2 + tid], s);
        g_rbC[tid] = s;
    }
    if (tid >= 128 && tid < 130) {
        int j = tid - 128;
        float s = 0.f;
        #pragma unroll
        for (int h = 0; h < 64; h++) s = fmaf(b1m[h], Wf[h * 2 + j], s);
        g_rbM[j] = s;
    }
}

// ---- FUSED (both relations in ONE grid):
//   gather(mean feat rows per dst) -> smem A tile ->
//   h = lrelu(A @ W0 + b0*gate)  [3xTF32 tensor-core GEMM]
//   p = h @ q + rb  (2 outputs/row)
// smem floats: sA[64*132] | sW[128*72] | sb[64] | sq[128] | sg[64] | srb[2] | sp[256]
#define FUSED_SMEM_FLOATS (64*SA_PITCH + 128*SW_PITCH + 64 + 128 + 64 + 2 + 256)
__global__ __launch_bounds__(256) void fused_both_kernel(
    const float* __restrict__ feat,
    const float* __restrict__ W0c, const float* __restrict__ b0c,
    const float* __restrict__ W0m, const float* __restrict__ b0m)
{
    extern __shared__ float smem[];
    float* sA  = smem;                       // 64 x SA_PITCH
    float* sW  = sA + 64 * SA_PITCH;         // 128 x SW_PITCH
    float* sb  = sW + 128 * SW_PITCH;
    float* sq  = sb + 64;
    float* sg  = sq + 128;
    float* srb = sg + 64;
    float* sp  = srb + 2;                    // [64 rows][2 halves][2 comps]

    const bool isC = blockIdx.x < NBF_C;
    const int blk = isC ? blockIdx.x : blockIdx.x - NBF_C;
    const int M = isC ? NCN : NMN;
    const int* __restrict__ perm = isC ? g_permC : g_permM;
    const int* __restrict__ base = isC ? g_baseC : g_baseM;
    const int* __restrict__ cnt  = isC ? g_cntC  : g_cntM;
    const float* __restrict__ W0 = isC ? W0c : W0m;
    const float* __restrict__ b0 = isC ? b0c : b0m;
    const float* __restrict__ q  = isC ? g_qC : g_qM;
    const float* __restrict__ rb = isC ? g_rbC : g_rbM;
    float* __restrict__ p_out    = isC ? g_pC : g_pM;

    const int tid = threadIdx.x;
    const int row0 = blk * 64;

    // cooperative load of W0 (8192 floats, padded pitch) + small vectors
    #pragma unroll
    for (int l = 0; l < 32; l++) {
        int idx = l * 256 + tid;
        int r = idx >> 6, c = idx & 63;
        sW[r * SW_PITCH + c] = W0[idx];
    }
    if (tid < 64) sb[tid] = b0[tid];
    else if (tid < 192) sq[tid - 64] = q[tid - 64];
    else if (tid < 194) srb[tid - 192] = rb[tid - 192];

    // gather: each warp accumulates 8 dst rows directly into sA (mean-normalized)
    const int wid = tid >> 5, lane = tid & 31;
    #pragma unroll
    for (int i = 0; i < 8; i++) {
        int rl = wid * 8 + i;
        int gr = row0 + rl;
        float4 a0 = make_float4(0.f, 0.f, 0.f, 0.f);
        float4 a1 = make_float4(0.f, 0.f, 0.f, 0.f);
        float invd = 0.f, gate = 0.f;
        if (gr < M) {
            int b = base[gr];
            int c = cnt[gr];
            invd = 1.0f / (float)(c > 0 ? c : 1);
            gate = (c > 0) ? 1.0f : 0.0f;
            int e = 0;
            for (; e + 1 < c; e += 2) {
                int s0 = __ldg(&perm[b + e]);
                int s1 = __ldg(&perm[b + e + 1]);
                float4 v0 = *(const float4*)(feat + (size_t)s0 * 128 + lane * 4);
                float4 v1 = *(const float4*)(feat + (size_t)s1 * 128 + lane * 4);
                a0.x += v0.x; a0.y += v0.y; a0.z += v0.z; a0.w += v0.w;
                a1.x += v1.x; a1.y += v1.y; a1.z += v1.z; a1.w += v1.w;
            }
            if (e < c) {
                int s0 = __ldg(&perm[b + e]);
                float4 v0 = *(const float4*)(feat + (size_t)s0 * 128 + lane * 4);
                a0.x += v0.x; a0.y += v0.y; a0.z += v0.z; a0.w += v0.w;
            }
        }
        a0.x = (a0.x + a1.x) * invd;
        a0.y = (a0.y + a1.y) * invd;
        a0.z = (a0.z + a1.z) * invd;
        a0.w = (a0.w + a1.w) * invd;
        *(float4*)(sA + rl * SA_PITCH + lane * 4) = a0;
        if (lane == 0) sg[rl] = gate;
    }
    __syncthreads();

    // ---- GEMM 64x64 tile, K=128 via mma.sync m16n8k8 tf32 (3xTF32) ----
    // warp w: rows [16*(w>>1), +16), cols [32*(w&1), +32) as 4 n8 tiles.
    const int g  = lane >> 2;     // group id (0..7)
    const int tg = lane & 3;      // thread in group (0..3)
    const int r16   = (wid >> 1) * 16;
    const int nhalf = (wid & 1) * 32;

    float d[4][4];
    #pragma unroll
    for (int t = 0; t < 4; t++)
        #pragma unroll
        for (int j = 0; j < 4; j++) d[t][j] = 0.f;

    #pragma unroll
    for (int k0 = 0; k0 < 128; k0 += 8) {
        float a0r = sA[(r16 + g)     * SA_PITCH + k0 + tg];
        float a1r = sA[(r16 + g + 8) * SA_PITCH + k0 + tg];
        float a2r = sA[(r16 + g)     * SA_PITCH + k0 + 4 + tg];
        float a3r = sA[(r16 + g + 8) * SA_PITCH + k0 + 4 + tg];
        unsigned int ah0 = f2tf32(a0r), ah1 = f2tf32(a1r);
        unsigned int ah2 = f2tf32(a2r), ah3 = f2tf32(a3r);
        unsigned int al0 = f2tf32(a0r - __uint_as_float(ah0));
        unsigned int al1 = f2tf32(a1r - __uint_as_float(ah1));
        unsigned int al2 = f2tf32(a2r - __uint_as_float(ah2));
        unsigned int al3 = f2tf32(a3r - __uint_as_float(ah3));
        #pragma unroll
        for (int t = 0; t < 4; t++) {
            float b0r = sW[(k0 + tg)     * SW_PITCH + nhalf + t * 8 + g];
            float b1r = sW[(k0 + 4 + tg) * SW_PITCH + nhalf + t * 8 + g];
            unsigned int bh0 = f2tf32(b0r), bh1 = f2tf32(b1r);
            unsigned int bl0 = f2tf32(b0r - __uint_as_float(bh0));
            unsigned int bl1 = f2tf32(b1r - __uint_as_float(bh1));
            mma_tf32(d[t], ah0, ah1, ah2, ah3, bh0, bh1);
            mma_tf32(d[t], al0, al1, al2, al3, bh0, bh1);
            mma_tf32(d[t], ah0, ah1, ah2, ah3, bl0, bl1);
        }
    }

    // epilogue: bias-gate + lrelu + 2-d projection.
    // lane holds rows r16+g (d0,d1) and r16+g+8 (d2,d3), cols nhalf+t*8+2*tg+{0,1}
    {
        float gateA = sg[r16 + g];
        float gateB = sg[r16 + g + 8];
        float pa0 = 0.f, pa1 = 0.f, pb0 = 0.f, pb1 = 0.f;
        #pragma unroll
        for (int t = 0; t < 4; t++) {
            int col0 = nhalf + t * 8 + 2 * tg;
            int col1 = col0 + 1;
            float hA0 = d[t][0] + sb[col0] * gateA;
            float hA1 = d[t][1] + sb[col1] * gateA;
            float hB0 = d[t][2] + sb[col0] * gateB;
            float hB1 = d[t][3] + sb[col1] * gateB;
            hA0 = (hA0 > 0.f) ? hA0 : 0.01f * hA0;
            hA1 = (hA1 > 0.f) ? hA1 : 0.01f * hA1;
            hB0 = (hB0 > 0.f) ? hB0 : 0.01f * hB0;
            hB1 = (hB1 > 0.f) ? hB1 : 0.01f * hB1;
            pa0 = fmaf(hA0, sq[col0 * 2],     pa0);
            pa1 = fmaf(hA0, sq[col0 * 2 + 1], pa1);
            pa0 = fmaf(hA1, sq[col1 * 2],     pa0);
            pa1 = fmaf(hA1, sq[col1 * 2 + 1], pa1);
            pb0 = fmaf(hB0, sq[col0 * 2],     pb0);
            pb1 = fmaf(hB0, sq[col0 * 2 + 1], pb1);
            pb0 = fmaf(hB1, sq[col1 * 2],     pb0);
            pb1 = fmaf(hB1, sq[col1 * 2 + 1], pb1);
        }
        // reduce across the 4 lanes of each row group
        #pragma unroll
        for (int o = 1; o <= 2; o <<= 1) {
            pa0 += __shfl_xor_sync(0xffffffffu, pa0, o);
            pa1 += __shfl_xor_sync(0xffffffffu, pa1, o);
            pb0 += __shfl_xor_sync(0xffffffffu, pb0, o);
            pb1 += __shfl_xor_sync(0xffffffffu, pb1, o);
        }
        if (tg == 0) {
            int h = wid & 1;
            sp[(r16 + g)     * 4 + h * 2 + 0] = pa0;
            sp[(r16 + g)     * 4 + h * 2 + 1] = pa1;
            sp[(r16 + g + 8) * 4 + h * 2 + 0] = pb0;
            sp[(r16 + g + 8) * 4 + h * 2 + 1] = pb1;
        }
    }
    __syncthreads();

    if (tid < 64) {
        int r = row0 + tid;
        if (r < M) {
            float p0 = sp[tid * 4 + 0] + sp[tid * 4 + 2] + srb[0];
            float p1 = sp[tid * 4 + 1] + sp[tid * 4 + 3] + srb[1];
            p_out[(size_t)r * 2]     = p0;
            p_out[(size_t)r * 2 + 1] = p1;
        }
    }
}

// layer-1 scatter: both relations, one thread per edge, 8 B payload
__global__ __launch_bounds__(256) void scatter2_kernel(
    const int* __restrict__ s_c2t, const int* __restrict__ d_c2t,
    const int* __restrict__ s_m2t, const int* __restrict__ d_m2t,
    float* __restrict__ out)
{
    int i = blockIdx.x * blockDim.x + threadIdx.x;
    if (i >= 2 * EN) return;
    int s, d;
    const float* p;
    float w;
    if (i < EN) {
        s = s_c2t[i]; d = d_c2t[i];
        p = g_pC + (size_t)s * 2;
        w = g_invT1[d];
    } else {
        int e = i - EN;
        s = s_m2t[e]; d = d_m2t[e];
        p = g_pM + (size_t)s * 2;
        w = g_invT2[d];
    }
    float2 v = *(const float2*)p;
    red_add_v2(out + (size_t)d * 2, v.x * w, v.y * w);
}

// ---------------- launch ----------------
extern "C" void kernel_launch(void* const* d_in, const int* in_sizes, int n_in,
                              void* d_out, int out_size)
{
    (void)in_sizes; (void)n_in; (void)out_size;

    const float* feat   = (const float*)d_in[0];
    const int* s_c2t    = (const int*)d_in[3];
    const int* d_c2t    = (const int*)d_in[4];
    const int* s_m2t    = (const int*)d_in[5];
    const int* d_m2t    = (const int*)d_in[6];
    const int* s_t2c    = (const int*)d_in[7];
    const int* d_t2c    = (const int*)d_in[8];
    const int* s_t2m    = (const int*)d_in[9];
    const int* d_t2m    = (const int*)d_in[10];
    const float* W1_c2t = (const float*)d_in[13];
    const float* b1_c2t = (const float*)d_in[14];
    const float* W1_m2t = (const float*)d_in[17];
    const float* b1_m2t = (const float*)d_in[18];
    const float* W0_t2c = (const float*)d_in[19];
    const float* b0_t2c = (const float*)d_in[20];
    const float* W0_t2m = (const float*)d_in[23];
    const float* b0_t2m = (const float*)d_in[24];
    const float* Wf     = (const float*)d_in[27];
    const float* bf     = (const float*)d_in[28];
    float* out = (float*)d_out;

    void *cntC_p, *cntM_p, *cntT1_p, *cntT2_p;
    cudaGetSymbolAddress(&cntC_p,  g_cntC);
    cudaGetSymbolAddress(&cntM_p,  g_cntM);
    cudaGetSymbolAddress(&cntT1_p, g_cntT1);
    cudaGetSymbolAddress(&cntT2_p, g_cntT2);

    const int fused_smem = FUSED_SMEM_FLOATS * (int)sizeof(float);
    cudaFuncSetAttribute(fused_both_kernel,
                         cudaFuncAttributeMaxDynamicSharedMemorySize, fused_smem);

    cudaMemsetAsync(cntC_p,  0, sizeof(g_cntC),  0);
    cudaMemsetAsync(cntM_p,  0, sizeof(g_cntM),  0);
    cudaMemsetAsync(cntT1_p, 0, sizeof(g_cntT1), 0);
    cudaMemsetAsync(cntT2_p, 0, sizeof(g_cntT2), 0);

    count_all_kernel<<<(4 * EN + 255) / 256, 256>>>(d_c2t, d_m2t, d_t2c, d_t2m);
    precompute_q_kernel<<<1, 256>>>(W1_c2t, b1_c2t, W1_m2t, b1_m2t, Wf);
    inv_out_kernel<<<(NTN + 255) / 256, 256>>>(bf, out);

    // CSR build (C and M in the same launches)
    blocksum_both_kernel<<<NB_C + NB_M, 256>>>();
    scan_both_kernel<<<2, 512>>>();
    finalize_both_kernel<<<NB_C + NB_M, 256>>>();
    bucket_both_kernel<<<(2 * EN + 255) / 256, 256>>>(s_t2c, d_t2c, s_t2m, d_t2m);

    // fused gather + tensor-core GEMM + projection, both relations in one grid
    fused_both_kernel<<<NBF_C + NBF_M, 256, fused_smem>>>(
        feat, W0_t2c, b0_t2c, W0_t2m, b0_t2m);

    // layer-1 scatter straight into the output
    scatter2_kernel<<<(2 * EN + 255) / 256, 256>>>(s_c2t, d_c2t, s_m2t, d_m2t, out);
}

// round 15
// speedup vs baseline: 1.6067x; 1.1975x over previous
#include <cuda_runtime.h>

#define NTN 500000
#define NCN 100000
#define NMN 20000
#define EN  500000

#define NB_C ((NCN + 255) / 256)   // 391
#define NB_M ((NMN + 255) / 256)   // 79
#define NBF_C ((NCN + 63) / 64)    // 1563 fused blocks (clients)
#define NBF_M ((NMN + 63) / 64)    // 313  fused blocks (merchants)

#define SA_PITCH 132               // 64 rows x 132 (128 + pad 4) — conflict-free A frags

// ---------------- device scratch (no dynamic allocation allowed) ----------------
__device__ int   g_cntC[NCN];
__device__ int   g_cntM[NMN];
__device__ int   g_cntT1[NTN];
__device__ int   g_cntT2[NTN];
__device__ float g_invT1[NTN];
__device__ float g_invT2[NTN];
__device__ int   g_baseC[NCN];
__device__ int   g_baseM[NMN];
__device__ int   g_curC[NCN];
__device__ int   g_curM[NMN];
__device__ int   g_permC[EN];
__device__ int   g_permM[EN];
__device__ int   g_bsumC[512];
__device__ int   g_bbaseC[512];
__device__ int   g_bsumM[512];
__device__ int   g_bbaseM[512];
__device__ __align__(256) float g_pC[(size_t)NCN * 2];
__device__ __align__(256) float g_pM[(size_t)NMN * 2];
__device__ __align__(16)  float g_qC[128];    // W1_c2t @ Wf
__device__ __align__(16)  float g_qM[128];    // W1_m2t @ Wf
__device__ __align__(16)  float g_rbC[2];
__device__ __align__(16)  float g_rbM[2];

__device__ __forceinline__ void red_add_v2(float* addr, float x, float y) {
    asm volatile("red.global.add.v2.f32 [%0], {%1, %2};"
                 :: "l"(addr), "f"(x), "f"(y) : "memory");
}

// ---- tf32 tensor-core helpers ----
__device__ __forceinline__ unsigned int f2tf32(float x) {
    unsigned int r;
    asm("cvt.rna.tf32.f32 %0, %1;" : "=r"(r) : "f"(x));
    return r;
}
__device__ __forceinline__ void mma_tf32(float* d,
    unsigned int a0, unsigned int a1, unsigned int a2, unsigned int a3,
    unsigned int b0, unsigned int b1)
{
    asm volatile(
        "mma.sync.aligned.m16n8k8.row.col.f32.tf32.tf32.f32 "
        "{%0,%1,%2,%3}, {%4,%5,%6,%7}, {%8,%9}, {%0,%1,%2,%3};"
        : "+f"(d[0]), "+f"(d[1]), "+f"(d[2]), "+f"(d[3])
        : "r"(a0), "r"(a1), "r"(a2), "r"(a3), "r"(b0), "r"(b1));
}

// ---------------- kernels ----------------

// all four dst histograms in one launch
__global__ void count_all_kernel(const int* __restrict__ d_c2t, const int* __restrict__ d_m2t,
                                 const int* __restrict__ d_t2c, const int* __restrict__ d_t2m)
{
    int i = blockIdx.x * blockDim.x + threadIdx.x;
    if (i < EN)            atomicAdd(&g_cntT1[d_c2t[i]], 1);
    else if (i < 2 * EN)   atomicAdd(&g_cntT2[d_m2t[i - EN]], 1);
    else if (i < 3 * EN)   atomicAdd(&g_cntC[d_t2c[i - 2 * EN]], 1);
    else if (i < 4 * EN)   atomicAdd(&g_cntM[d_t2m[i - 3 * EN]], 1);
}

// inv weights for transactions + output init to bf
__global__ void inv_out_kernel(const float* __restrict__ bf, float* __restrict__ out)
{
    int i = blockIdx.x * blockDim.x + threadIdx.x;
    if (i < NTN) {
        int c1 = g_cntT1[i]; g_invT1[i] = 1.0f / (float)(c1 > 0 ? c1 : 1);
        int c2 = g_cntT2[i]; g_invT2[i] = 1.0f / (float)(c2 > 0 ? c2 : 1);
        ((float2*)out)[i] = make_float2(bf[0], bf[1]);
    }
}

// ---- CSR build (both relations in each launch) ----
__global__ void blocksum_both_kernel()
{
    __shared__ int s[256];
    bool isC = blockIdx.x < NB_C;
    int blk = isC ? blockIdx.x : blockIdx.x - NB_C;
    const int* cnt = isC ? g_cntC : g_cntM;
    int n = isC ? NCN : NMN;
    int i = blk * 256 + threadIdx.x;
    s[threadIdx.x] = (i < n) ? cnt[i] : 0;
    __syncthreads();
    #pragma unroll
    for (int o = 128; o > 0; o >>= 1) {
        if (threadIdx.x < o) s[threadIdx.x] += s[threadIdx.x + o];
        __syncthreads();
    }
    if (threadIdx.x == 0) (isC ? g_bsumC : g_bsumM)[blk] = s[0];
}

__global__ void scan_both_kernel()
{
    __shared__ int s[512];
    bool isC = blockIdx.x == 0;
    const int* bsum = isC ? g_bsumC : g_bsumM;
    int* bbase = isC ? g_bbaseC : g_bbaseM;
    int nb = isC ? NB_C : NB_M;
    int t = threadIdx.x;
    int v = (t < nb) ? bsum[t] : 0;
    s[t] = v;
    __syncthreads();
    #pragma unroll
    for (int o = 1; o < 512; o <<= 1) {
        int add = (t >= o) ? s[t - o] : 0;
        __syncthreads();
        s[t] += add;
        __syncthreads();
    }
    if (t < nb) bbase[t] = s[t] - v;   // exclusive
}

__global__ void finalize_both_kernel()
{
    __shared__ int s[256];
    bool isC = blockIdx.x < NB_C;
    int blk = isC ? blockIdx.x : blockIdx.x - NB_C;
    const int* cnt = isC ? g_cntC : g_cntM;
    const int* bbase = isC ? g_bbaseC : g_bbaseM;
    int* base = isC ? g_baseC : g_baseM;
    int* cur = isC ? g_curC : g_curM;
    int n = isC ? NCN : NMN;
    int t = threadIdx.x;
    int i = blk * 256 + t;
    int v = (i < n) ? cnt[i] : 0;
    s[t] = v;
    __syncthreads();
    #pragma unroll
    for (int o = 1; o < 256; o <<= 1) {
        int add = (t >= o) ? s[t - o] : 0;
        __syncthreads();
        s[t] += add;
        __syncthreads();
    }
    if (i < n) {
        int b = bbase[blk] + s[t] - v;
        base[i] = b;
        cur[i]  = b;
    }
}

__global__ void bucket_both_kernel(const int* __restrict__ s_t2c, const int* __restrict__ d_t2c,
                                   const int* __restrict__ s_t2m, const int* __restrict__ d_t2m)
{
    int i = blockIdx.x * blockDim.x + threadIdx.x;
    if (i < EN) {
        int d = d_t2c[i];
        int pos = atomicAdd(&g_curC[d], 1);
        g_permC[pos] = s_t2c[i];
    } else if (i < 2 * EN) {
        int e = i - EN;
        int d = d_t2m[e];
        int pos = atomicAdd(&g_curM[d], 1);
        g_permM[pos] = s_t2m[e];
    }
}

// q = W1 @ Wf (64x64 @ 64x2), rb = b1 @ Wf — tiny, one block
__global__ void precompute_q_kernel(const float* __restrict__ W1c, const float* __restrict__ b1c,
                                    const float* __restrict__ W1m, const float* __restrict__ b1m,
                                    const float* __restrict__ Wf)
{
    int tid = threadIdx.x;  // 256 threads
    if (tid < 128) {
        int k = tid >> 1, j = tid & 1;
        float s = 0.f;
        #pragma unroll
        for (int h = 0; h < 64; h++) s = fmaf(W1c[k * 64 + h], Wf[h * 2 + j], s);
        g_qC[tid] = s;
    } else {
        int t = tid - 128;
        int k = t >> 1, j = t & 1;
        float s = 0.f;
        #pragma unroll
        for (int h = 0; h < 64; h++) s = fmaf(W1m[k * 64 + h], Wf[h * 2 + j], s);
        g_qM[t] = s;
    }
    if (tid < 2) {
        float s = 0.f;
        #pragma unroll
        for (int h = 0; h < 64; h++) s = fmaf(b1c[h], Wf[h * 2 + tid], s);
        g_rbC[tid] = s;
    }
    if (tid >= 128 && tid < 130) {
        int j = tid - 128;
        float s = 0.f;
        #pragma unroll
        for (int h = 0; h < 64; h++) s = fmaf(b1m[h], Wf[h * 2 + j], s);
        g_rbM[j] = s;
    }
}

// ---- FUSED (both relations in ONE grid):
//   gather(mean feat rows per dst) -> smem A tile ->
//   h = lrelu(A @ W0 + b0*gate)  [3xTF32 tensor-core GEMM, B direct from L1]
//   p = h @ q + rb  (2 outputs/row)
// smem floats: sA[64*132] | sb[64] | sq[128] | sg[64] | srb[2] | sp[256]
// (~35.9 KB — 4 blocks/SM with launch_bounds(256,4) for gather MLP)
#define FUSED_SMEM_FLOATS (64*SA_PITCH + 64 + 128 + 64 + 2 + 256)
__global__ __launch_bounds__(256, 4) void fused_both_kernel(
    const float* __restrict__ feat,
    const float* __restrict__ W0c, const float* __restrict__ b0c,
    const float* __restrict__ W0m, const float* __restrict__ b0m)
{
    extern __shared__ float smem[];
    float* sA  = smem;                       // 64 x SA_PITCH
    float* sb  = sA + 64 * SA_PITCH;
    float* sq  = sb + 64;
    float* sg  = sq + 128;
    float* srb = sg + 64;
    float* sp  = srb + 2;                    // [64 rows][2 halves][2 comps]

    const bool isC = blockIdx.x < NBF_C;
    const int blk = isC ? blockIdx.x : blockIdx.x - NBF_C;
    const int M = isC ? NCN : NMN;
    const int* __restrict__ perm = isC ? g_permC : g_permM;
    const int* __restrict__ base = isC ? g_baseC : g_baseM;
    const int* __restrict__ cnt  = isC ? g_cntC  : g_cntM;
    const float* __restrict__ W0 = isC ? W0c : W0m;
    const float* __restrict__ b0 = isC ? b0c : b0m;
    const float* __restrict__ q  = isC ? g_qC : g_qM;
    const float* __restrict__ rb = isC ? g_rbC : g_rbM;
    float* __restrict__ p_out    = isC ? g_pC : g_pM;

    const int tid = threadIdx.x;
    const int row0 = blk * 64;

    // small vectors into smem
    if (tid < 64) sb[tid] = b0[tid];
    else if (tid < 192) sq[tid - 64] = q[tid - 64];
    else if (tid < 194) srb[tid - 192] = rb[tid - 192];

    // gather: each warp accumulates 8 dst rows into sA (mean-normalized), MLP=4
    const int wid = tid >> 5, lane = tid & 31;
    #pragma unroll
    for (int i = 0; i < 8; i++) {
        int rl = wid * 8 + i;
        int gr = row0 + rl;
        float4 a0 = make_float4(0.f, 0.f, 0.f, 0.f);
        float4 a1 = make_float4(0.f, 0.f, 0.f, 0.f);
        float4 a2 = make_float4(0.f, 0.f, 0.f, 0.f);
        float4 a3 = make_float4(0.f, 0.f, 0.f, 0.f);
        float invd = 0.f, gate = 0.f;
        if (gr < M) {
            int b = base[gr];
            int c = cnt[gr];
            invd = 1.0f / (float)(c > 0 ? c : 1);
            gate = (c > 0) ? 1.0f : 0.0f;
            int e = 0;
            for (; e + 3 < c; e += 4) {
                int s0 = __ldg(&perm[b + e]);
                int s1 = __ldg(&perm[b + e + 1]);
                int s2 = __ldg(&perm[b + e + 2]);
                int s3 = __ldg(&perm[b + e + 3]);
                float4 v0 = *(const float4*)(feat + (size_t)s0 * 128 + lane * 4);
                float4 v1 = *(const float4*)(feat + (size_t)s1 * 128 + lane * 4);
                float4 v2 = *(const float4*)(feat + (size_t)s2 * 128 + lane * 4);
                float4 v3 = *(const float4*)(feat + (size_t)s3 * 128 + lane * 4);
                a0.x += v0.x; a0.y += v0.y; a0.z += v0.z; a0.w += v0.w;
                a1.x += v1.x; a1.y += v1.y; a1.z += v1.z; a1.w += v1.w;
                a2.x += v2.x; a2.y += v2.y; a2.z += v2.z; a2.w += v2.w;
                a3.x += v3.x; a3.y += v3.y; a3.z += v3.z; a3.w += v3.w;
            }
            for (; e < c; e++) {
                int s0 = __ldg(&perm[b + e]);
                float4 v0 = *(const float4*)(feat + (size_t)s0 * 128 + lane * 4);
                a0.x += v0.x; a0.y += v0.y; a0.z += v0.z; a0.w += v0.w;
            }
        }
        a0.x = (a0.x + a1.x + a2.x + a3.x) * invd;
        a0.y = (a0.y + a1.y + a2.y + a3.y) * invd;
        a0.z = (a0.z + a1.z + a2.z + a3.z) * invd;
        a0.w = (a0.w + a1.w + a2.w + a3.w) * invd;
        *(float4*)(sA + rl * SA_PITCH + lane * 4) = a0;
        if (lane == 0) sg[rl] = gate;
    }
    __syncthreads();

    // ---- GEMM 64x64 tile, K=128 via mma.sync m16n8k8 tf32 (3xTF32) ----
    // B fragments straight from global (W0 is 32 KB, L1-resident).
    const int g  = lane >> 2;     // group id (0..7)
    const int tg = lane & 3;      // thread in group (0..3)
    const int r16   = (wid >> 1) * 16;
    const int nhalf = (wid & 1) * 32;

    float d[4][4];
    #pragma unroll
    for (int t = 0; t < 4; t++)
        #pragma unroll
        for (int j = 0; j < 4; j++) d[t][j] = 0.f;

    #pragma unroll
    for (int k0 = 0; k0 < 128; k0 += 8) {
        float a0r = sA[(r16 + g)     * SA_PITCH + k0 + tg];
        float a1r = sA[(r16 + g + 8) * SA_PITCH + k0 + tg];
        float a2r = sA[(r16 + g)     * SA_PITCH + k0 + 4 + tg];
        float a3r = sA[(r16 + g + 8) * SA_PITCH + k0 + 4 + tg];
        unsigned int ah0 = f2tf32(a0r), ah1 = f2tf32(a1r);
        unsigned int ah2 = f2tf32(a2r), ah3 = f2tf32(a3r);
        unsigned int al0 = f2tf32(a0r - __uint_as_float(ah0));
        unsigned int al1 = f2tf32(a1r - __uint_as_float(ah1));
        unsigned int al2 = f2tf32(a2r - __uint_as_float(ah2));
        unsigned int al3 = f2tf32(a3r - __uint_as_float(ah3));
        #pragma unroll
        for (int t = 0; t < 4; t++) {
            int col = nhalf + t * 8 + g;
            float b0r = __ldg(&W0[(k0 + tg)     * 64 + col]);
            float b1r = __ldg(&W0[(k0 + 4 + tg) * 64 + col]);
            unsigned int bh0 = f2tf32(b0r), bh1 = f2tf32(b1r);
            unsigned int bl0 = f2tf32(b0r - __uint_as_float(bh0));
            unsigned int bl1 = f2tf32(b1r - __uint_as_float(bh1));
            mma_tf32(d[t], ah0, ah1, ah2, ah3, bh0, bh1);
            mma_tf32(d[t], al0, al1, al2, al3, bh0, bh1);
            mma_tf32(d[t], ah0, ah1, ah2, ah3, bl0, bl1);
        }
    }

    // epilogue: bias-gate + lrelu + 2-d projection.
    {
        float gateA = sg[r16 + g];
        float gateB = sg[r16 + g + 8];
        float pa0 = 0.f, pa1 = 0.f, pb0 = 0.f, pb1 = 0.f;
        #pragma unroll
        for (int t = 0; t < 4; t++) {
            int col0 = nhalf + t * 8 + 2 * tg;
            int col1 = col0 + 1;
            float hA0 = d[t][0] + sb[col0] * gateA;
            float hA1 = d[t][1] + sb[col1] * gateA;
            float hB0 = d[t][2] + sb[col0] * gateB;
            float hB1 = d[t][3] + sb[col1] * gateB;
            hA0 = (hA0 > 0.f) ? hA0 : 0.01f * hA0;
            hA1 = (hA1 > 0.f) ? hA1 : 0.01f * hA1;
            hB0 = (hB0 > 0.f) ? hB0 : 0.01f * hB0;
            hB1 = (hB1 > 0.f) ? hB1 : 0.01f * hB1;
            pa0 = fmaf(hA0, sq[col0 * 2],     pa0);
            pa1 = fmaf(hA0, sq[col0 * 2 + 1], pa1);
            pa0 = fmaf(hA1, sq[col1 * 2],     pa0);
            pa1 = fmaf(hA1, sq[col1 * 2 + 1], pa1);
            pb0 = fmaf(hB0, sq[col0 * 2],     pb0);
            pb1 = fmaf(hB0, sq[col0 * 2 + 1], pb1);
            pb0 = fmaf(hB1, sq[col1 * 2],     pb0);
            pb1 = fmaf(hB1, sq[col1 * 2 + 1], pb1);
        }
        #pragma unroll
        for (int o = 1; o <= 2; o <<= 1) {
            pa0 += __shfl_xor_sync(0xffffffffu, pa0, o);
            pa1 += __shfl_xor_sync(0xffffffffu, pa1, o);
            pb0 += __shfl_xor_sync(0xffffffffu, pb0, o);
            pb1 += __shfl_xor_sync(0xffffffffu, pb1, o);
        }
        if (tg == 0) {
            int h = wid & 1;
            sp[(r16 + g)     * 4 + h * 2 + 0] = pa0;
            sp[(r16 + g)     * 4 + h * 2 + 1] = pa1;
            sp[(r16 + g + 8) * 4 + h * 2 + 0] = pb0;
            sp[(r16 + g + 8) * 4 + h * 2 + 1] = pb1;
        }
    }
    __syncthreads();

    if (tid < 64) {
        int r = row0 + tid;
        if (r < M) {
            float p0 = sp[tid * 4 + 0] + sp[tid * 4 + 2] + srb[0];
            float p1 = sp[tid * 4 + 1] + sp[tid * 4 + 3] + srb[1];
            p_out[(size_t)r * 2]     = p0;
            p_out[(size_t)r * 2 + 1] = p1;
        }
    }
}

// layer-1 scatter: both relations, one thread per edge, 8 B payload
__global__ __launch_bounds__(256) void scatter2_kernel(
    const int* __restrict__ s_c2t, const int* __restrict__ d_c2t,
    const int* __restrict__ s_m2t, const int* __restrict__ d_m2t,
    float* __restrict__ out)
{
    int i = blockIdx.x * blockDim.x + threadIdx.x;
    if (i >= 2 * EN) return;
    int s, d;
    const float* p;
    float w;
    if (i < EN) {
        s = s_c2t[i]; d = d_c2t[i];
        p = g_pC + (size_t)s * 2;
        w = g_invT1[d];
    } else {
        int e = i - EN;
        s = s_m2t[e]; d = d_m2t[e];
        p = g_pM + (size_t)s * 2;
        w = g_invT2[d];
    }
    float2 v = *(const float2*)p;
    red_add_v2(out + (size_t)d * 2, v.x * w, v.y * w);
}

// ---------------- launch ----------------
extern "C" void kernel_launch(void* const* d_in, const int* in_sizes, int n_in,
                              void* d_out, int out_size)
{
    (void)in_sizes; (void)n_in; (void)out_size;

    const float* feat   = (const float*)d_in[0];
    const int* s_c2t    = (const int*)d_in[3];
    const int* d_c2t    = (const int*)d_in[4];
    const int* s_m2t    = (const int*)d_in[5];
    const int* d_m2t    = (const int*)d_in[6];
    const int* s_t2c    = (const int*)d_in[7];
    const int* d_t2c    = (const int*)d_in[8];
    const int* s_t2m    = (const int*)d_in[9];
    const int* d_t2m    = (const int*)d_in[10];
    const float* W1_c2t = (const float*)d_in[13];
    const float* b1_c2t = (const float*)d_in[14];
    const float* W1_m2t = (const float*)d_in[17];
    const float* b1_m2t = (const float*)d_in[18];
    const float* W0_t2c = (const float*)d_in[19];
    const float* b0_t2c = (const float*)d_in[20];
    const float* W0_t2m = (const float*)d_in[23];
    const float* b0_t2m = (const float*)d_in[24];
    const float* Wf     = (const float*)d_in[27];
    const float* bf     = (const float*)d_in[28];
    float* out = (float*)d_out;

    void *cntC_p, *cntM_p, *cntT1_p, *cntT2_p;
    cudaGetSymbolAddress(&cntC_p,  g_cntC);
    cudaGetSymbolAddress(&cntM_p,  g_cntM);
    cudaGetSymbolAddress(&cntT1_p, g_cntT1);
    cudaGetSymbolAddress(&cntT2_p, g_cntT2);

    const int fused_smem = FUSED_SMEM_FLOATS * (int)sizeof(float);
    cudaFuncSetAttribute(fused_both_kernel,
                         cudaFuncAttributeMaxDynamicSharedMemorySize, fused_smem);

    cudaMemsetAsync(cntC_p,  0, sizeof(g_cntC),  0);
    cudaMemsetAsync(cntM_p,  0, sizeof(g_cntM),  0);
    cudaMemsetAsync(cntT1_p, 0, sizeof(g_cntT1), 0);
    cudaMemsetAsync(cntT2_p, 0, sizeof(g_cntT2), 0);

    count_all_kernel<<<(4 * EN + 255) / 256, 256>>>(d_c2t, d_m2t, d_t2c, d_t2m);
    precompute_q_kernel<<<1, 256>>>(W1_c2t, b1_c2t, W1_m2t, b1_m2t, Wf);
    inv_out_kernel<<<(NTN + 255) / 256, 256>>>(bf, out);

    // CSR build (C and M in the same launches)
    blocksum_both_kernel<<<NB_C + NB_M, 256>>>();
    scan_both_kernel<<<2, 512>>>();
    finalize_both_kernel<<<NB_C + NB_M, 256>>>();
    bucket_both_kernel<<<(2 * EN + 255) / 256, 256>>>(s_t2c, d_t2c, s_t2m, d_t2m);

    // fused gather + tensor-core GEMM + projection, both relations in one grid
    fused_both_kernel<<<NBF_C + NBF_M, 256, fused_smem>>>(
        feat, W0_t2c, b0_t2c, W0_t2m, b0_t2m);

    // layer-1 scatter straight into the output
    scatter2_kernel<<<(2 * EN + 255) / 256, 256>>>(s_c2t, d_c2t, s_m2t, d_m2t, out);
}

// round 16
// speedup vs baseline: 1.6838x; 1.0480x over previous
#include <cuda_runtime.h>

#define NTN 500000
#define NCN 100000
#define NMN 20000
#define EN  500000

#define NB_C ((NCN + 255) / 256)   // 391
#define NB_M ((NMN + 255) / 256)   // 79
#define NBF_C ((NCN + 63) / 64)    // 1563 fused blocks (clients)
#define NBF_M ((NMN + 63) / 64)    // 313  fused blocks (merchants)

#define SA_PITCH 132               // 64 rows x 132 (128 + pad 4) — conflict-free A frags

#define SCAT_BLOCKS ((2 * EN + 255) / 256)          // 3907
#define ZERO_INT4   ((NCN + NMN + 2 * NTN) / 4)     // 280000 int4 to zero
#define ZERO_BLOCKS ((ZERO_INT4 + 255) / 256)       // 1094
#define BKT_BLOCKS  ((2 * EN + 255) / 256)          // 3907
#define INV_BLOCKS  ((NTN + 255) / 256)             // 1954

// ---------------- device scratch (no dynamic allocation allowed) ----------------
// NOTE: counter arrays rely on (a) zero-init at module load and (b) re-zeroing
// by scatter2's tail blocks at the end of every replay (they are dead by then).
__device__ int   g_cntC[NCN];
__device__ int   g_cntM[NMN];
__device__ int   g_cntT1[NTN];
__device__ int   g_cntT2[NTN];
__device__ float g_invT1[NTN];
__device__ float g_invT2[NTN];
__device__ int   g_baseC[NCN];
__device__ int   g_baseM[NMN];
__device__ int   g_curC[NCN];
__device__ int   g_curM[NMN];
__device__ int   g_permC[EN];
__device__ int   g_permM[EN];
__device__ int   g_bsumC[512];
__device__ int   g_bbaseC[512];
__device__ int   g_bsumM[512];
__device__ int   g_bbaseM[512];
__device__ __align__(256) float g_pC[(size_t)NCN * 2];
__device__ __align__(256) float g_pM[(size_t)NMN * 2];
__device__ __align__(16)  float g_qC[128];    // W1_c2t @ Wf
__device__ __align__(16)  float g_qM[128];    // W1_m2t @ Wf
__device__ __align__(16)  float g_rbC[2];
__device__ __align__(16)  float g_rbM[2];

__device__ __forceinline__ void red_add_v2(float* addr, float x, float y) {
    asm volatile("red.global.add.v2.f32 [%0], {%1, %2};"
                 :: "l"(addr), "f"(x), "f"(y) : "memory");
}

// ---- tf32 tensor-core helpers ----
__device__ __forceinline__ unsigned int f2tf32(float x) {
    unsigned int r;
    asm("cvt.rna.tf32.f32 %0, %1;" : "=r"(r) : "f"(x));
    return r;
}
__device__ __forceinline__ void mma_tf32(float* d,
    unsigned int a0, unsigned int a1, unsigned int a2, unsigned int a3,
    unsigned int b0, unsigned int b1)
{
    asm volatile(
        "mma.sync.aligned.m16n8k8.row.col.f32.tf32.tf32.f32 "
        "{%0,%1,%2,%3}, {%4,%5,%6,%7}, {%8,%9}, {%0,%1,%2,%3};"
        : "+f"(d[0]), "+f"(d[1]), "+f"(d[2]), "+f"(d[3])
        : "r"(a0), "r"(a1), "r"(a2), "r"(a3), "r"(b0), "r"(b1));
}

// ---------------- kernels ----------------

// all four dst histograms in one launch (counters pre-zeroed by previous replay)
__global__ void count_all_kernel(const int* __restrict__ d_c2t, const int* __restrict__ d_m2t,
                                 const int* __restrict__ d_t2c, const int* __restrict__ d_t2m)
{
    int i = blockIdx.x * blockDim.x + threadIdx.x;
    if (i < EN)            atomicAdd(&g_cntT1[d_c2t[i]], 1);
    else if (i < 2 * EN)   atomicAdd(&g_cntT2[d_m2t[i - EN]], 1);
    else if (i < 3 * EN)   atomicAdd(&g_cntC[d_t2c[i - 2 * EN]], 1);
    else if (i < 4 * EN)   atomicAdd(&g_cntM[d_t2m[i - 3 * EN]], 1);
}

// ---- CSR build (both relations in each launch) ----
__global__ void blocksum_both_kernel()
{
    __shared__ int s[256];
    bool isC = blockIdx.x < NB_C;
    int blk = isC ? blockIdx.x : blockIdx.x - NB_C;
    const int* cnt = isC ? g_cntC : g_cntM;
    int n = isC ? NCN : NMN;
    int i = blk * 256 + threadIdx.x;
    s[threadIdx.x] = (i < n) ? cnt[i] : 0;
    __syncthreads();
    #pragma unroll
    for (int o = 128; o > 0; o >>= 1) {
        if (threadIdx.x < o) s[threadIdx.x] += s[threadIdx.x + o];
        __syncthreads();
    }
    if (threadIdx.x == 0) (isC ? g_bsumC : g_bsumM)[blk] = s[0];
}

__global__ void scan_both_kernel()
{
    __shared__ int s[512];
    bool isC = blockIdx.x == 0;
    const int* bsum = isC ? g_bsumC : g_bsumM;
    int* bbase = isC ? g_bbaseC : g_bbaseM;
    int nb = isC ? NB_C : NB_M;
    int t = threadIdx.x;
    int v = (t < nb) ? bsum[t] : 0;
    s[t] = v;
    __syncthreads();
    #pragma unroll
    for (int o = 1; o < 512; o <<= 1) {
        int add = (t >= o) ? s[t - o] : 0;
        __syncthreads();
        s[t] += add;
        __syncthreads();
    }
    if (t < nb) bbase[t] = s[t] - v;   // exclusive
}

__global__ void finalize_both_kernel()
{
    __shared__ int s[256];
    bool isC = blockIdx.x < NB_C;
    int blk = isC ? blockIdx.x : blockIdx.x - NB_C;
    const int* cnt = isC ? g_cntC : g_cntM;
    const int* bbase = isC ? g_bbaseC : g_bbaseM;
    int* base = isC ? g_baseC : g_baseM;
    int* cur = isC ? g_curC : g_curM;
    int n = isC ? NCN : NMN;
    int t = threadIdx.x;
    int i = blk * 256 + t;
    int v = (i < n) ? cnt[i] : 0;
    s[t] = v;
    __syncthreads();
    #pragma unroll
    for (int o = 1; o < 256; o <<= 1) {
        int add = (t >= o) ? s[t - o] : 0;
        __syncthreads();
        s[t] += add;
        __syncthreads();
    }
    if (i < n) {
        int b = bbase[blk] + s[t] - v;
        base[i] = b;
        cur[i]  = b;
    }
}

// edge counting-sort (both relations) + transaction inv weights + out init
__global__ __launch_bounds__(256) void bucket_inv_kernel(
    const int* __restrict__ s_t2c, const int* __restrict__ d_t2c,
    const int* __restrict__ s_t2m, const int* __restrict__ d_t2m,
    const float* __restrict__ bf, float* __restrict__ out)
{
    if (blockIdx.x < BKT_BLOCKS) {
        int i = blockIdx.x * 256 + threadIdx.x;
        if (i < EN) {
            int d = d_t2c[i];
            int pos = atomicAdd(&g_curC[d], 1);
            g_permC[pos] = s_t2c[i];
        } else if (i < 2 * EN) {
            int e = i - EN;
            int d = d_t2m[e];
            int pos = atomicAdd(&g_curM[d], 1);
            g_permM[pos] = s_t2m[e];
        }
    } else {
        int i = (blockIdx.x - BKT_BLOCKS) * 256 + threadIdx.x;
        if (i < NTN) {
            int c1 = g_cntT1[i]; g_invT1[i] = 1.0f / (float)(c1 > 0 ? c1 : 1);
            int c2 = g_cntT2[i]; g_invT2[i] = 1.0f / (float)(c2 > 0 ? c2 : 1);
            ((float2*)out)[i] = make_float2(bf[0], bf[1]);
        }
    }
}

// q = W1 @ Wf (64x64 @ 64x2), rb = b1 @ Wf — tiny, one block
__global__ void precompute_q_kernel(const float* __restrict__ W1c, const float* __restrict__ b1c,
                                    const float* __restrict__ W1m, const float* __restrict__ b1m,
                                    const float* __restrict__ Wf)
{
    int tid = threadIdx.x;  // 256 threads
    if (tid < 128) {
        int k = tid >> 1, j = tid & 1;
        float s = 0.f;
        #pragma unroll
        for (int h = 0; h < 64; h++) s = fmaf(W1c[k * 64 + h], Wf[h * 2 + j], s);
        g_qC[tid] = s;
    } else {
        int t = tid - 128;
        int k = t >> 1, j = t & 1;
        float s = 0.f;
        #pragma unroll
        for (int h = 0; h < 64; h++) s = fmaf(W1m[k * 64 + h], Wf[h * 2 + j], s);
        g_qM[t] = s;
    }
    if (tid < 2) {
        float s = 0.f;
        #pragma unroll
        for (int h = 0; h < 64; h++) s = fmaf(b1c[h], Wf[h * 2 + tid], s);
        g_rbC[tid] = s;
    }
    if (tid >= 128 && tid < 130) {
        int j = tid - 128;
        float s = 0.f;
        #pragma unroll
        for (int h = 0; h < 64; h++) s = fmaf(b1m[h], Wf[h * 2 + j], s);
        g_rbM[j] = s;
    }
}

// ---- FUSED (both relations in ONE grid):
//   gather(mean feat rows per dst) -> smem A tile ->
//   h = lrelu(A @ W0 + b0*gate)  [3xTF32 tensor-core GEMM, B direct from L1]
//   p = h @ q + rb  (2 outputs/row)
// smem floats: sA[64*132] | sb[64] | sq[128] | sg[64] | srb[2] | sp[256]
// (~35.9 KB — 4 blocks/SM with launch_bounds(256,4) for gather MLP)
#define FUSED_SMEM_FLOATS (64*SA_PITCH + 64 + 128 + 64 + 2 + 256)
__global__ __launch_bounds__(256, 4) void fused_both_kernel(
    const float* __restrict__ feat,
    const float* __restrict__ W0c, const float* __restrict__ b0c,
    const float* __restrict__ W0m, const float* __restrict__ b0m)
{
    extern __shared__ float smem[];
    float* sA  = smem;                       // 64 x SA_PITCH
    float* sb  = sA + 64 * SA_PITCH;
    float* sq  = sb + 64;
    float* sg  = sq + 128;
    float* srb = sg + 64;
    float* sp  = srb + 2;                    // [64 rows][2 halves][2 comps]

    const bool isC = blockIdx.x < NBF_C;
    const int blk = isC ? blockIdx.x : blockIdx.x - NBF_C;
    const int M = isC ? NCN : NMN;
    const int* __restrict__ perm = isC ? g_permC : g_permM;
    const int* __restrict__ base = isC ? g_baseC : g_baseM;
    const int* __restrict__ cnt  = isC ? g_cntC  : g_cntM;
    const float* __restrict__ W0 = isC ? W0c : W0m;
    const float* __restrict__ b0 = isC ? b0c : b0m;
    const float* __restrict__ q  = isC ? g_qC : g_qM;
    const float* __restrict__ rb = isC ? g_rbC : g_rbM;
    float* __restrict__ p_out    = isC ? g_pC : g_pM;

    const int tid = threadIdx.x;
    const int row0 = blk * 64;

    // small vectors into smem
    if (tid < 64) sb[tid] = b0[tid];
    else if (tid < 192) sq[tid - 64] = q[tid - 64];
    else if (tid < 194) srb[tid - 192] = rb[tid - 192];

    // gather: each warp accumulates 8 dst rows into sA (mean-normalized), MLP=4
    const int wid = tid >> 5, lane = tid & 31;
    #pragma unroll
    for (int i = 0; i < 8; i++) {
        int rl = wid * 8 + i;
        int gr = row0 + rl;
        float4 a0 = make_float4(0.f, 0.f, 0.f, 0.f);
        float4 a1 = make_float4(0.f, 0.f, 0.f, 0.f);
        float4 a2 = make_float4(0.f, 0.f, 0.f, 0.f);
        float4 a3 = make_float4(0.f, 0.f, 0.f, 0.f);
        float invd = 0.f, gate = 0.f;
        if (gr < M) {
            int b = base[gr];
            int c = cnt[gr];
            invd = 1.0f / (float)(c > 0 ? c : 1);
            gate = (c > 0) ? 1.0f : 0.0f;
            int e = 0;
            for (; e + 3 < c; e += 4) {
                int s0 = __ldg(&perm[b + e]);
                int s1 = __ldg(&perm[b + e + 1]);
                int s2 = __ldg(&perm[b + e + 2]);
                int s3 = __ldg(&perm[b + e + 3]);
                float4 v0 = *(const float4*)(feat + (size_t)s0 * 128 + lane * 4);
                float4 v1 = *(const float4*)(feat + (size_t)s1 * 128 + lane * 4);
                float4 v2 = *(const float4*)(feat + (size_t)s2 * 128 + lane * 4);
                float4 v3 = *(const float4*)(feat + (size_t)s3 * 128 + lane * 4);
                a0.x += v0.x; a0.y += v0.y; a0.z += v0.z; a0.w += v0.w;
                a1.x += v1.x; a1.y += v1.y; a1.z += v1.z; a1.w += v1.w;
                a2.x += v2.x; a2.y += v2.y; a2.z += v2.z; a2.w += v2.w;
                a3.x += v3.x; a3.y += v3.y; a3.z += v3.z; a3.w += v3.w;
            }
            for (; e < c; e++) {
                int s0 = __ldg(&perm[b + e]);
                float4 v0 = *(const float4*)(feat + (size_t)s0 * 128 + lane * 4);
                a0.x += v0.x; a0.y += v0.y; a0.z += v0.z; a0.w += v0.w;
            }
        }
        a0.x = (a0.x + a1.x + a2.x + a3.x) * invd;
        a0.y = (a0.y + a1.y + a2.y + a3.y) * invd;
        a0.z = (a0.z + a1.z + a2.z + a3.z) * invd;
        a0.w = (a0.w + a1.w + a2.w + a3.w) * invd;
        *(float4*)(sA + rl * SA_PITCH + lane * 4) = a0;
        if (lane == 0) sg[rl] = gate;
    }
    __syncthreads();

    // ---- GEMM 64x64 tile, K=128 via mma.sync m16n8k8 tf32 (3xTF32) ----
    // B fragments straight from global (W0 is 32 KB, L1-resident).
    const int g  = lane >> 2;     // group id (0..7)
    const int tg = lane & 3;      // thread in group (0..3)
    const int r16   = (wid >> 1) * 16;
    const int nhalf = (wid & 1) * 32;

    float d[4][4];
    #pragma unroll
    for (int t = 0; t < 4; t++)
        #pragma unroll
        for (int j = 0; j < 4; j++) d[t][j] = 0.f;

    #pragma unroll
    for (int k0 = 0; k0 < 128; k0 += 8) {
        float a0r = sA[(r16 + g)     * SA_PITCH + k0 + tg];
        float a1r = sA[(r16 + g + 8) * SA_PITCH + k0 + tg];
        float a2r = sA[(r16 + g)     * SA_PITCH + k0 + 4 + tg];
        float a3r = sA[(r16 + g + 8) * SA_PITCH + k0 + 4 + tg];
        unsigned int ah0 = f2tf32(a0r), ah1 = f2tf32(a1r);
        unsigned int ah2 = f2tf32(a2r), ah3 = f2tf32(a3r);
        unsigned int al0 = f2tf32(a0r - __uint_as_float(ah0));
        unsigned int al1 = f2tf32(a1r - __uint_as_float(ah1));
        unsigned int al2 = f2tf32(a2r - __uint_as_float(ah2));
        unsigned int al3 = f2tf32(a3r - __uint_as_float(ah3));
        #pragma unroll
        for (int t = 0; t < 4; t++) {
            int col = nhalf + t * 8 + g;
            float b0r = __ldg(&W0[(k0 + tg)     * 64 + col]);
            float b1r = __ldg(&W0[(k0 + 4 + tg) * 64 + col]);
            unsigned int bh0 = f2tf32(b0r), bh1 = f2tf32(b1r);
            unsigned int bl0 = f2tf32(b0r - __uint_as_float(bh0));
            unsigned int bl1 = f2tf32(b1r - __uint_as_float(bh1));
            mma_tf32(d[t], ah0, ah1, ah2, ah3, bh0, bh1);
            mma_tf32(d[t], al0, al1, al2, al3, bh0, bh1);
            mma_tf32(d[t], ah0, ah1, ah2, ah3, bl0, bl1);
        }
    }

    // epilogue: bias-gate + lrelu + 2-d projection.
    {
        float gateA = sg[r16 + g];
        float gateB = sg[r16 + g + 8];
        float pa0 = 0.f, pa1 = 0.f, pb0 = 0.f, pb1 = 0.f;
        #pragma unroll
        for (int t = 0; t < 4; t++) {
            int col0 = nhalf + t * 8 + 2 * tg;
            int col1 = col0 + 1;
            float hA0 = d[t][0] + sb[col0] * gateA;
            float hA1 = d[t][1] + sb[col1] * gateA;
            float hB0 = d[t][2] + sb[col0] * gateB;
            float hB1 = d[t][3] + sb[col1] * gateB;
            hA0 = (hA0 > 0.f) ? hA0 : 0.01f * hA0;
            hA1 = (hA1 > 0.f) ? hA1 : 0.01f * hA1;
            hB0 = (hB0 > 0.f) ? hB0 : 0.01f * hB0;
            hB1 = (hB1 > 0.f) ? hB1 : 0.01f * hB1;
            pa0 = fmaf(hA0, sq[col0 * 2],     pa0);
            pa1 = fmaf(hA0, sq[col0 * 2 + 1], pa1);
            pa0 = fmaf(hA1, sq[col1 * 2],     pa0);
            pa1 = fmaf(hA1, sq[col1 * 2 + 1], pa1);
            pb0 = fmaf(hB0, sq[col0 * 2],     pb0);
            pb1 = fmaf(hB0, sq[col0 * 2 + 1], pb1);
            pb0 = fmaf(hB1, sq[col1 * 2],     pb0);
            pb1 = fmaf(hB1, sq[col1 * 2 + 1], pb1);
        }
        #pragma unroll
        for (int o = 1; o <= 2; o <<= 1) {
            pa0 += __shfl_xor_sync(0xffffffffu, pa0, o);
            pa1 += __shfl_xor_sync(0xffffffffu, pa1, o);
            pb0 += __shfl_xor_sync(0xffffffffu, pb0, o);
            pb1 += __shfl_xor_sync(0xffffffffu, pb1, o);
        }
        if (tg == 0) {
            int h = wid & 1;
            sp[(r16 + g)     * 4 + h * 2 + 0] = pa0;
            sp[(r16 + g)     * 4 + h * 2 + 1] = pa1;
            sp[(r16 + g + 8) * 4 + h * 2 + 0] = pb0;
            sp[(r16 + g + 8) * 4 + h * 2 + 1] = pb1;
        }
    }
    __syncthreads();

    if (tid < 64) {
        int r = row0 + tid;
        if (r < M) {
            float p0 = sp[tid * 4 + 0] + sp[tid * 4 + 2] + srb[0];
            float p1 = sp[tid * 4 + 1] + sp[tid * 4 + 3] + srb[1];
            p_out[(size_t)r * 2]     = p0;
            p_out[(size_t)r * 2 + 1] = p1;
        }
    }
}

// layer-1 scatter (both relations) + tail blocks re-zero the counter arrays
// for the NEXT replay (they are dead at this point in the pipeline).
__global__ __launch_bounds__(256) void scatter2_zero_kernel(
    const int* __restrict__ s_c2t, const int* __restrict__ d_c2t,
    const int* __restrict__ s_m2t, const int* __restrict__ d_m2t,
    float* __restrict__ out)
{
    if (blockIdx.x < SCAT_BLOCKS) {
        int i = blockIdx.x * 256 + threadIdx.x;
        if (i >= 2 * EN) return;
        int s, d;
        const float* p;
        float w;
        if (i < EN) {
            s = s_c2t[i]; d = d_c2t[i];
            p = g_pC + (size_t)s * 2;
            w = g_invT1[d];
        } else {
            int e = i - EN;
            s = s_m2t[e]; d = d_m2t[e];
            p = g_pM + (size_t)s * 2;
            w = g_invT2[d];
        }
        float2 v = *(const float2*)p;
        red_add_v2(out + (size_t)d * 2, v.x * w, v.y * w);
    } else {
        int idx = (blockIdx.x - SCAT_BLOCKS) * 256 + threadIdx.x;   // int4 index
        const int4 z = make_int4(0, 0, 0, 0);
        const int nC = NCN / 4, nM = NMN / 4, nT = NTN / 4;
        if (idx < nC)                    ((int4*)g_cntC)[idx] = z;
        else if (idx < nC + nM)          ((int4*)g_cntM)[idx - nC] = z;
        else if (idx < nC + nM + nT)     ((int4*)g_cntT1)[idx - nC - nM] = z;
        else if (idx < nC + nM + 2*nT)   ((int4*)g_cntT2)[idx - nC - nM - nT] = z;
    }
}

// ---------------- launch ----------------
extern "C" void kernel_launch(void* const* d_in, const int* in_sizes, int n_in,
                              void* d_out, int out_size)
{
    (void)in_sizes; (void)n_in; (void)out_size;

    const float* feat   = (const float*)d_in[0];
    const int* s_c2t    = (const int*)d_in[3];
    const int* d_c2t    = (const int*)d_in[4];
    const int* s_m2t    = (const int*)d_in[5];
    const int* d_m2t    = (const int*)d_in[6];
    const int* s_t2c    = (const int*)d_in[7];
    const int* d_t2c    = (const int*)d_in[8];
    const int* s_t2m    = (const int*)d_in[9];
    const int* d_t2m    = (const int*)d_in[10];
    const float* W1_c2t = (const float*)d_in[13];
    const float* b1_c2t = (const float*)d_in[14];
    const float* W1_m2t = (const float*)d_in[17];
    const float* b1_m2t = (const float*)d_in[18];
    const float* W0_t2c = (const float*)d_in[19];
    const float* b0_t2c = (const float*)d_in[20];
    const float* W0_t2m = (const float*)d_in[23];
    const float* b0_t2m = (const float*)d_in[24];
    const float* Wf     = (const float*)d_in[27];
    const float* bf     = (const float*)d_in[28];
    float* out = (float*)d_out;

    const int fused_smem = FUSED_SMEM_FLOATS * (int)sizeof(float);
    cudaFuncSetAttribute(fused_both_kernel,
                         cudaFuncAttributeMaxDynamicSharedMemorySize, fused_smem);

    // counters arrive zeroed: module-load zero-init on the first call,
    // re-zeroed by scatter2_zero's tail on every subsequent call/replay.
    count_all_kernel<<<(4 * EN + 255) / 256, 256>>>(d_c2t, d_m2t, d_t2c, d_t2m);
    precompute_q_kernel<<<1, 256>>>(W1_c2t, b1_c2t, W1_m2t, b1_m2t, Wf);

    // CSR build (C and M in the same launches)
    blocksum_both_kernel<<<NB_C + NB_M, 256>>>();
    scan_both_kernel<<<2, 512>>>();
    finalize_both_kernel<<<NB_C + NB_M, 256>>>();

    // counting-sort edges + transaction inv weights + out init (one grid)
    bucket_inv_kernel<<<BKT_BLOCKS + INV_BLOCKS, 256>>>(
        s_t2c, d_t2c, s_t2m, d_t2m, bf, out);

    // fused gather + tensor-core GEMM + projection, both relations in one grid
    fused_both_kernel<<<NBF_C + NBF_M, 256, fused_smem>>>(
        feat, W0_t2c, b0_t2c, W0_t2m, b0_t2m);

    // layer-1 scatter into the output + counter re-zero for next replay
    scatter2_zero_kernel<<<SCAT_BLOCKS + ZERO_BLOCKS, 256>>>(
        s_c2t, d_c2t, s_m2t, d_m2t, out);
}

// round 17
// speedup vs baseline: 1.7458x; 1.0369x over previous
#include <cuda_runtime.h>

#define NTN 500000
#define NCN 100000
#define NMN 20000
#define EN  500000

#define NB_C ((NCN + 255) / 256)   // 391
#define NB_M ((NMN + 255) / 256)   // 79
#define NBF_C ((NCN + 63) / 64)    // 1563 fused blocks (clients)
#define NBF_M ((NMN + 63) / 64)    // 313  fused blocks (merchants)

#define SA_PITCH 132               // 64 rows x 132 (128 + pad 4) — conflict-free A frags

#define CNT_BLOCKS  ((4 * EN + 255) / 256)          // 7813
#define SCAT_BLOCKS ((2 * EN + 255) / 256)          // 3907
#define ZERO_INT4   ((NCN + NMN + 2 * NTN) / 4)     // 280000 int4 to zero
#define ZERO_BLOCKS ((ZERO_INT4 + 255) / 256)       // 1094
#define BKT_BLOCKS  ((2 * EN + 255) / 256)          // 3907
#define INV_BLOCKS  ((NTN + 255) / 256)             // 1954

// ---------------- device scratch (no dynamic allocation allowed) ----------------
// NOTE: counter arrays rely on (a) zero-init at module load and (b) re-zeroing
// by scatter2's tail blocks at the end of every replay (they are dead by then).
__device__ int   g_cntC[NCN];
__device__ int   g_cntM[NMN];
__device__ int   g_cntT1[NTN];
__device__ int   g_cntT2[NTN];
__device__ float g_invT1[NTN];
__device__ float g_invT2[NTN];
__device__ int   g_baseC[NCN];
__device__ int   g_baseM[NMN];
__device__ int   g_curC[NCN];
__device__ int   g_curM[NMN];
__device__ int   g_permC[EN];
__device__ int   g_permM[EN];
__device__ int   g_bsumC[512];
__device__ int   g_bbaseC[512];
__device__ int   g_bsumM[512];
__device__ int   g_bbaseM[512];
__device__ __align__(256) float g_pC[(size_t)NCN * 2];
__device__ __align__(256) float g_pM[(size_t)NMN * 2];
__device__ __align__(16)  float g_qC[128];    // W1_c2t @ Wf
__device__ __align__(16)  float g_qM[128];    // W1_m2t @ Wf
__device__ __align__(16)  float g_rbC[2];
__device__ __align__(16)  float g_rbM[2];

__device__ __forceinline__ void red_add_v2(float* addr, float x, float y) {
    asm volatile("red.global.add.v2.f32 [%0], {%1, %2};"
                 :: "l"(addr), "f"(x), "f"(y) : "memory");
}

// ---- tf32 tensor-core helpers ----
__device__ __forceinline__ unsigned int f2tf32(float x) {
    unsigned int r;
    asm("cvt.rna.tf32.f32 %0, %1;" : "=r"(r) : "f"(x));
    return r;
}
__device__ __forceinline__ void mma_tf32(float* d,
    unsigned int a0, unsigned int a1, unsigned int a2, unsigned int a3,
    unsigned int b0, unsigned int b1)
{
    asm volatile(
        "mma.sync.aligned.m16n8k8.row.col.f32.tf32.tf32.f32 "
        "{%0,%1,%2,%3}, {%4,%5,%6,%7}, {%8,%9}, {%0,%1,%2,%3};"
        : "+f"(d[0]), "+f"(d[1]), "+f"(d[2]), "+f"(d[3])
        : "r"(a0), "r"(a1), "r"(a2), "r"(a3), "r"(b0), "r"(b1));
}

// ---------------- kernels ----------------

// all four dst histograms + q/rb precompute (tail block) in one launch
__global__ void count_q_kernel(const int* __restrict__ d_c2t, const int* __restrict__ d_m2t,
                               const int* __restrict__ d_t2c, const int* __restrict__ d_t2m,
                               const float* __restrict__ W1c, const float* __restrict__ b1c,
                               const float* __restrict__ W1m, const float* __restrict__ b1m,
                               const float* __restrict__ Wf)
{
    if (blockIdx.x < CNT_BLOCKS) {
        int i = blockIdx.x * 256 + threadIdx.x;
        if (i < EN)            atomicAdd(&g_cntT1[d_c2t[i]], 1);
        else if (i < 2 * EN)   atomicAdd(&g_cntT2[d_m2t[i - EN]], 1);
        else if (i < 3 * EN)   atomicAdd(&g_cntC[d_t2c[i - 2 * EN]], 1);
        else if (i < 4 * EN)   atomicAdd(&g_cntM[d_t2m[i - 3 * EN]], 1);
        return;
    }
    // tail block: q = W1 @ Wf, rb = b1 @ Wf
    int tid = threadIdx.x;
    if (tid < 128) {
        int k = tid >> 1, j = tid & 1;
        float s = 0.f;
        #pragma unroll
        for (int h = 0; h < 64; h++) s = fmaf(W1c[k * 64 + h], Wf[h * 2 + j], s);
        g_qC[tid] = s;
    } else {
        int t = tid - 128;
        int k = t >> 1, j = t & 1;
        float s = 0.f;
        #pragma unroll
        for (int h = 0; h < 64; h++) s = fmaf(W1m[k * 64 + h], Wf[h * 2 + j], s);
        g_qM[t] = s;
    }
    if (tid < 2) {
        float s = 0.f;
        #pragma unroll
        for (int h = 0; h < 64; h++) s = fmaf(b1c[h], Wf[h * 2 + tid], s);
        g_rbC[tid] = s;
    }
    if (tid >= 128 && tid < 130) {
        int j = tid - 128;
        float s = 0.f;
        #pragma unroll
        for (int h = 0; h < 64; h++) s = fmaf(b1m[h], Wf[h * 2 + j], s);
        g_rbM[j] = s;
    }
}

// ---- CSR build (both relations in each launch) ----
__global__ void blocksum_both_kernel()
{
    __shared__ int s[256];
    bool isC = blockIdx.x < NB_C;
    int blk = isC ? blockIdx.x : blockIdx.x - NB_C;
    const int* cnt = isC ? g_cntC : g_cntM;
    int n = isC ? NCN : NMN;
    int i = blk * 256 + threadIdx.x;
    s[threadIdx.x] = (i < n) ? cnt[i] : 0;
    __syncthreads();
    #pragma unroll
    for (int o = 128; o > 0; o >>= 1) {
        if (threadIdx.x < o) s[threadIdx.x] += s[threadIdx.x + o];
        __syncthreads();
    }
    if (threadIdx.x == 0) (isC ? g_bsumC : g_bsumM)[blk] = s[0];
}

__global__ void scan_both_kernel()
{
    __shared__ int s[512];
    bool isC = blockIdx.x == 0;
    const int* bsum = isC ? g_bsumC : g_bsumM;
    int* bbase = isC ? g_bbaseC : g_bbaseM;
    int nb = isC ? NB_C : NB_M;
    int t = threadIdx.x;
    int v = (t < nb) ? bsum[t] : 0;
    s[t] = v;
    __syncthreads();
    #pragma unroll
    for (int o = 1; o < 512; o <<= 1) {
        int add = (t >= o) ? s[t - o] : 0;
        __syncthreads();
        s[t] += add;
        __syncthreads();
    }
    if (t < nb) bbase[t] = s[t] - v;   // exclusive
}

__global__ void finalize_both_kernel()
{
    __shared__ int s[256];
    bool isC = blockIdx.x < NB_C;
    int blk = isC ? blockIdx.x : blockIdx.x - NB_C;
    const int* cnt = isC ? g_cntC : g_cntM;
    const int* bbase = isC ? g_bbaseC : g_bbaseM;
    int* base = isC ? g_baseC : g_baseM;
    int* cur = isC ? g_curC : g_curM;
    int n = isC ? NCN : NMN;
    int t = threadIdx.x;
    int i = blk * 256 + t;
    int v = (i < n) ? cnt[i] : 0;
    s[t] = v;
    __syncthreads();
    #pragma unroll
    for (int o = 1; o < 256; o <<= 1) {
        int add = (t >= o) ? s[t - o] : 0;
        __syncthreads();
        s[t] += add;
        __syncthreads();
    }
    if (i < n) {
        int b = bbase[blk] + s[t] - v;
        base[i] = b;
        cur[i]  = b;
    }
}

// edge counting-sort (both relations) + transaction inv weights + out init
__global__ __launch_bounds__(256) void bucket_inv_kernel(
    const int* __restrict__ s_t2c, const int* __restrict__ d_t2c,
    const int* __restrict__ s_t2m, const int* __restrict__ d_t2m,
    const float* __restrict__ bf, float* __restrict__ out)
{
    if (blockIdx.x < BKT_BLOCKS) {
        int i = blockIdx.x * 256 + threadIdx.x;
        if (i < EN) {
            int d = d_t2c[i];
            int pos = atomicAdd(&g_curC[d], 1);
            g_permC[pos] = s_t2c[i];
        } else if (i < 2 * EN) {
            int e = i - EN;
            int d = d_t2m[e];
            int pos = atomicAdd(&g_curM[d], 1);
            g_permM[pos] = s_t2m[e];
        }
    } else {
        int i = (blockIdx.x - BKT_BLOCKS) * 256 + threadIdx.x;
        if (i < NTN) {
            int c1 = g_cntT1[i]; g_invT1[i] = 1.0f / (float)(c1 > 0 ? c1 : 1);
            int c2 = g_cntT2[i]; g_invT2[i] = 1.0f / (float)(c2 > 0 ? c2 : 1);
            ((float2*)out)[i] = make_float2(bf[0], bf[1]);
        }
    }
}

// ---- FUSED (both relations in ONE grid):
//   gather(mean feat rows per dst) -> smem A tile ->
//   h = lrelu(A @ W0 + b0*gate)  [3xTF32 tensor-core GEMM, B direct from L1]
//   p = h @ q + rb  (2 outputs/row)
// smem floats: sA[64*132] | sb[64] | sq[128] | sg[64] | srb[2] | sp[256]
// (~35.9 KB — 4 blocks/SM with launch_bounds(256,4) for gather MLP)
#define FUSED_SMEM_FLOATS (64*SA_PITCH + 64 + 128 + 64 + 2 + 256)
__global__ __launch_bounds__(256, 4) void fused_both_kernel(
    const float* __restrict__ feat,
    const float* __restrict__ W0c, const float* __restrict__ b0c,
    const float* __restrict__ W0m, const float* __restrict__ b0m)
{
    extern __shared__ float smem[];
    float* sA  = smem;                       // 64 x SA_PITCH
    float* sb  = sA + 64 * SA_PITCH;
    float* sq  = sb + 64;
    float* sg  = sq + 128;
    float* srb = sg + 64;
    float* sp  = srb + 2;                    // [64 rows][2 halves][2 comps]

    const bool isC = blockIdx.x < NBF_C;
    const int blk = isC ? blockIdx.x : blockIdx.x - NBF_C;
    const int M = isC ? NCN : NMN;
    const int* __restrict__ perm = isC ? g_permC : g_permM;
    const int* __restrict__ base = isC ? g_baseC : g_baseM;
    const int* __restrict__ cnt  = isC ? g_cntC  : g_cntM;
    const float* __restrict__ W0 = isC ? W0c : W0m;
    const float* __restrict__ b0 = isC ? b0c : b0m;
    const float* __restrict__ q  = isC ? g_qC : g_qM;
    const float* __restrict__ rb = isC ? g_rbC : g_rbM;
    float* __restrict__ p_out    = isC ? g_pC : g_pM;

    const int tid = threadIdx.x;
    const int row0 = blk * 64;

    // small vectors into smem
    if (tid < 64) sb[tid] = b0[tid];
    else if (tid < 192) sq[tid - 64] = q[tid - 64];
    else if (tid < 194) srb[tid - 192] = rb[tid - 192];

    // gather: each warp accumulates 8 dst rows into sA (mean-normalized).
    // 4-wide predicated chunks: partial chunks keep MLP≈4 (no serial remainder).
    const int wid = tid >> 5, lane = tid & 31;
    #pragma unroll
    for (int i = 0; i < 8; i++) {
        int rl = wid * 8 + i;
        int gr = row0 + rl;
        float4 a0 = make_float4(0.f, 0.f, 0.f, 0.f);
        float4 a1 = make_float4(0.f, 0.f, 0.f, 0.f);
        float4 a2 = make_float4(0.f, 0.f, 0.f, 0.f);
        float4 a3 = make_float4(0.f, 0.f, 0.f, 0.f);
        float invd = 0.f, gate = 0.f;
        if (gr < M) {
            int b = base[gr];
            int c = cnt[gr];
            invd = 1.0f / (float)(c > 0 ? c : 1);
            gate = (c > 0) ? 1.0f : 0.0f;
            for (int e = 0; e < c; e += 4) {
                int s0 = __ldg(&perm[b + e]);
                float4 v0 = *(const float4*)(feat + (size_t)s0 * 128 + lane * 4);
                a0.x += v0.x; a0.y += v0.y; a0.z += v0.z; a0.w += v0.w;
                if (e + 1 < c) {
                    int s1 = __ldg(&perm[b + e + 1]);
                    float4 v1 = *(const float4*)(feat + (size_t)s1 * 128 + lane * 4);
                    a1.x += v1.x; a1.y += v1.y; a1.z += v1.z; a1.w += v1.w;
                }
                if (e + 2 < c) {
                    int s2 = __ldg(&perm[b + e + 2]);
                    float4 v2 = *(const float4*)(feat + (size_t)s2 * 128 + lane * 4);
                    a2.x += v2.x; a2.y += v2.y; a2.z += v2.z; a2.w += v2.w;
                }
                if (e + 3 < c) {
                    int s3 = __ldg(&perm[b + e + 3]);
                    float4 v3 = *(const float4*)(feat + (size_t)s3 * 128 + lane * 4);
                    a3.x += v3.x; a3.y += v3.y; a3.z += v3.z; a3.w += v3.w;
                }
            }
        }
        a0.x = (a0.x + a1.x + a2.x + a3.x) * invd;
        a0.y = (a0.y + a1.y + a2.y + a3.y) * invd;
        a0.z = (a0.z + a1.z + a2.z + a3.z) * invd;
        a0.w = (a0.w + a1.w + a2.w + a3.w) * invd;
        *(float4*)(sA + rl * SA_PITCH + lane * 4) = a0;
        if (lane == 0) sg[rl] = gate;
    }
    __syncthreads();

    // ---- GEMM 64x64 tile, K=128 via mma.sync m16n8k8 tf32 (3xTF32) ----
    // B fragments straight from global (W0 is 32 KB, L1-resident).
    const int g  = lane >> 2;     // group id (0..7)
    const int tg = lane & 3;      // thread in group (0..3)
    const int r16   = (wid >> 1) * 16;
    const int nhalf = (wid & 1) * 32;

    float d[4][4];
    #pragma unroll
    for (int t = 0; t < 4; t++)
        #pragma unroll
        for (int j = 0; j < 4; j++) d[t][j] = 0.f;

    #pragma unroll
    for (int k0 = 0; k0 < 128; k0 += 8) {
        float a0r = sA[(r16 + g)     * SA_PITCH + k0 + tg];
        float a1r = sA[(r16 + g + 8) * SA_PITCH + k0 + tg];
        float a2r = sA[(r16 + g)     * SA_PITCH + k0 + 4 + tg];
        float a3r = sA[(r16 + g + 8) * SA_PITCH + k0 + 4 + tg];
        unsigned int ah0 = f2tf32(a0r), ah1 = f2tf32(a1r);
        unsigned int ah2 = f2tf32(a2r), ah3 = f2tf32(a3r);
        unsigned int al0 = f2tf32(a0r - __uint_as_float(ah0));
        unsigned int al1 = f2tf32(a1r - __uint_as_float(ah1));
        unsigned int al2 = f2tf32(a2r - __uint_as_float(ah2));
        unsigned int al3 = f2tf32(a3r - __uint_as_float(ah3));
        #pragma unroll
        for (int t = 0; t < 4; t++) {
            int col = nhalf + t * 8 + g;
            float b0r = __ldg(&W0[(k0 + tg)     * 64 + col]);
            float b1r = __ldg(&W0[(k0 + 4 + tg) * 64 + col]);
            unsigned int bh0 = f2tf32(b0r), bh1 = f2tf32(b1r);
            unsigned int bl0 = f2tf32(b0r - __uint_as_float(bh0));
            unsigned int bl1 = f2tf32(b1r - __uint_as_float(bh1));
            mma_tf32(d[t], ah0, ah1, ah2, ah3, bh0, bh1);
            mma_tf32(d[t], al0, al1, al2, al3, bh0, bh1);
            mma_tf32(d[t], ah0, ah1, ah2, ah3, bl0, bl1);
        }
    }

    // epilogue: bias-gate + lrelu + 2-d projection.
    {
        float gateA = sg[r16 + g];
        float gateB = sg[r16 + g + 8];
        float pa0 = 0.f, pa1 = 0.f, pb0 = 0.f, pb1 = 0.f;
        #pragma unroll
        for (int t = 0; t < 4; t++) {
            int col0 = nhalf + t * 8 + 2 * tg;
            int col1 = col0 + 1;
            float hA0 = d[t][0] + sb[col0] * gateA;
            float hA1 = d[t][1] + sb[col1] * gateA;
            float hB0 = d[t][2] + sb[col0] * gateB;
            float hB1 = d[t][3] + sb[col1] * gateB;
            hA0 = (hA0 > 0.f) ? hA0 : 0.01f * hA0;
            hA1 = (hA1 > 0.f) ? hA1 : 0.01f * hA1;
            hB0 = (hB0 > 0.f) ? hB0 : 0.01f * hB0;
            hB1 = (hB1 > 0.f) ? hB1 : 0.01f * hB1;
            pa0 = fmaf(hA0, sq[col0 * 2],     pa0);
            pa1 = fmaf(hA0, sq[col0 * 2 + 1], pa1);
            pa0 = fmaf(hA1, sq[col1 * 2],     pa0);
            pa1 = fmaf(hA1, sq[col1 * 2 + 1], pa1);
            pb0 = fmaf(hB0, sq[col0 * 2],     pb0);
            pb1 = fmaf(hB0, sq[col0 * 2 + 1], pb1);
            pb0 = fmaf(hB1, sq[col1 * 2],     pb0);
            pb1 = fmaf(hB1, sq[col1 * 2 + 1], pb1);
        }
        #pragma unroll
        for (int o = 1; o <= 2; o <<= 1) {
            pa0 += __shfl_xor_sync(0xffffffffu, pa0, o);
            pa1 += __shfl_xor_sync(0xffffffffu, pa1, o);
            pb0 += __shfl_xor_sync(0xffffffffu, pb0, o);
            pb1 += __shfl_xor_sync(0xffffffffu, pb1, o);
        }
        if (tg == 0) {
            int h = wid & 1;
            sp[(r16 + g)     * 4 + h * 2 + 0] = pa0;
            sp[(r16 + g)     * 4 + h * 2 + 1] = pa1;
            sp[(r16 + g + 8) * 4 + h * 2 + 0] = pb0;
            sp[(r16 + g + 8) * 4 + h * 2 + 1] = pb1;
        }
    }
    __syncthreads();

    if (tid < 64) {
        int r = row0 + tid;
        if (r < M) {
            float p0 = sp[tid * 4 + 0] + sp[tid * 4 + 2] + srb[0];
            float p1 = sp[tid * 4 + 1] + sp[tid * 4 + 3] + srb[1];
            p_out[(size_t)r * 2]     = p0;
            p_out[(size_t)r * 2 + 1] = p1;
        }
    }
}

// layer-1 scatter (both relations) + tail blocks re-zero the counter arrays
// for the NEXT replay (they are dead at this point in the pipeline).
__global__ __launch_bounds__(256) void scatter2_zero_kernel(
    const int* __restrict__ s_c2t, const int* __restrict__ d_c2t,
    const int* __restrict__ s_m2t, const int* __restrict__ d_m2t,
    float* __restrict__ out)
{
    if (blockIdx.x < SCAT_BLOCKS) {
        int i = blockIdx.x * 256 + threadIdx.x;
        if (i >= 2 * EN) return;
        int s, d;
        const float* p;
        float w;
        if (i < EN) {
            s = s_c2t[i]; d = d_c2t[i];
            p = g_pC + (size_t)s * 2;
            w = g_invT1[d];
        } else {
            int e = i - EN;
            s = s_m2t[e]; d = d_m2t[e];
            p = g_pM + (size_t)s * 2;
            w = g_invT2[d];
        }
        float2 v = *(const float2*)p;
        red_add_v2(out + (size_t)d * 2, v.x * w, v.y * w);
    } else {
        int idx = (blockIdx.x - SCAT_BLOCKS) * 256 + threadIdx.x;   // int4 index
        const int4 z = make_int4(0, 0, 0, 0);
        const int nC = NCN / 4, nM = NMN / 4, nT = NTN / 4;
        if (idx < nC)                    ((int4*)g_cntC)[idx] = z;
        else if (idx < nC + nM)          ((int4*)g_cntM)[idx - nC] = z;
        else if (idx < nC + nM + nT)     ((int4*)g_cntT1)[idx - nC - nM] = z;
        else if (idx < nC + nM + 2*nT)   ((int4*)g_cntT2)[idx - nC - nM - nT] = z;
    }
}

// ---------------- launch ----------------
extern "C" void kernel_launch(void* const* d_in, const int* in_sizes, int n_in,
                              void* d_out, int out_size)
{
    (void)in_sizes; (void)n_in; (void)out_size;

    const float* feat   = (const float*)d_in[0];
    const int* s_c2t    = (const int*)d_in[3];
    const int* d_c2t    = (const int*)d_in[4];
    const int* s_m2t    = (const int*)d_in[5];
    const int* d_m2t    = (const int*)d_in[6];
    const int* s_t2c    = (const int*)d_in[7];
    const int* d_t2c    = (const int*)d_in[8];
    const int* s_t2m    = (const int*)d_in[9];
    const int* d_t2m    = (const int*)d_in[10];
    const float* W1_c2t = (const float*)d_in[13];
    const float* b1_c2t = (const float*)d_in[14];
    const float* W1_m2t = (const float*)d_in[17];
    const float* b1_m2t = (const float*)d_in[18];
    const float* W0_t2c = (const float*)d_in[19];
    const float* b0_t2c = (const float*)d_in[20];
    const float* W0_t2m = (const float*)d_in[23];
    const float* b0_t2m = (const float*)d_in[24];
    const float* Wf     = (const float*)d_in[27];
    const float* bf     = (const float*)d_in[28];
    float* out = (float*)d_out;

    const int fused_smem = FUSED_SMEM_FLOATS * (int)sizeof(float);
    cudaFuncSetAttribute(fused_both_kernel,
                         cudaFuncAttributeMaxDynamicSharedMemorySize, fused_smem);

    // counters arrive zeroed: module-load zero-init on the first call,
    // re-zeroed by scatter2_zero's tail on every subsequent call/replay.
    count_q_kernel<<<CNT_BLOCKS + 1, 256>>>(
        d_c2t, d_m2t, d_t2c, d_t2m, W1_c2t, b1_c2t, W1_m2t, b1_m2t, Wf);

    // CSR build (C and M in the same launches)
    blocksum_both_kernel<<<NB_C + NB_M, 256>>>();
    scan_both_kernel<<<2, 512>>>();
    finalize_both_kernel<<<NB_C + NB_M, 256>>>();

    // counting-sort edges + transaction inv weights + out init (one grid)
    bucket_inv_kernel<<<BKT_BLOCKS + INV_BLOCKS, 256>>>(
        s_t2c, d_t2c, s_t2m, d_t2m, bf, out);

    // fused gather + tensor-core GEMM + projection, both relations in one grid
    fused_both_kernel<<<NBF_C + NBF_M, 256, fused_smem>>>(
        feat, W0_t2c, b0_t2c, W0_t2m, b0_t2m);

    // layer-1 scatter into the output + counter re-zero for next replay
    scatter2_zero_kernel<<<SCAT_BLOCKS + ZERO_BLOCKS, 256>>>(
        s_c2t, d_c2t, s_m2t, d_m2t, out);
}